// round 14
// baseline (speedup 1.0000x reference)
#include <cuda_runtime.h>
#include <cuda_fp16.h>
#include <math.h>
#include <stdint.h>

#define NN_   4096
#define EE_   131072
#define IN_   500
#define HH_   500
#define OUT_  100
#define CC_   15451
#define CCP_  15488
#define NHEAD 4
#define HD_   125
#define HDP_  128
#define KP500 512
#define NKT   (NN_ / 64)

// ---------------- scratch ----------------------------------------------------
__device__ int    g_degi[NN_];
__device__ int    g_off[NN_ + 1];
__device__ int    g_cur[NN_];
__device__ int    g_csr[EE_];
__device__ __half g_xh[NN_ * KP500];
__device__ __half g_meanh[NN_ * KP500];
__device__ __half g_h1h[NN_ * KP500];
__device__ __half g_attnoh[NN_ * KP500];   // pads (cols 500..511) stay zero forever
__device__ __half g_h2h[NN_ * KP500];
__device__ float  g_tmp2[NN_ * OUT_];
__device__ __half g_outxh[NN_ * 128];

__device__ __half g_qh[NHEAD * NN_ * HDP_];   // pads d=125..127 stay zero forever
__device__ __half g_ql[NHEAD * NN_ * HDP_];
__device__ __half g_kh[NHEAD * NN_ * HDP_];
__device__ __half g_kl[NHEAD * NN_ * HDP_];
__device__ __half g_vt[NHEAD * HDP_ * NN_];   // pad rows d=125..127 stay zero forever

__device__ __half g_w1sh[HH_ * KP500], g_w1sl[HH_ * KP500];
__device__ __half g_w1nh[HH_ * KP500], g_w1nl[HH_ * KP500];
__device__ __half g_winh[3 * HH_ * KP500], g_winl[3 * HH_ * KP500];
__device__ __half g_woh[HH_ * KP500], g_wol[HH_ * KP500];
__device__ __half g_w2sh[OUT_ * KP500], g_w2sl[OUT_ * KP500];
__device__ __half g_w2nh[OUT_ * KP500], g_w2nl[OUT_ * KP500];
__device__ __half g_wch[(size_t)CC_ * 128], g_wcl[(size_t)CC_ * 128];

// ---------------- helpers ----------------------------------------------------
__device__ __forceinline__ void splitf_h(float x, __half& h, __half& l) {
    h = __float2half_rn(x);
    l = __float2half_rn(x - __half2float(h));
}
__device__ __forceinline__ void split2h(float x, float y, uint32_t& hi, uint32_t& lo) {
    __half hx = __float2half_rn(x), hy = __float2half_rn(y);
    __half lx = __float2half_rn(x - __half2float(hx));
    __half ly = __float2half_rn(y - __half2float(hy));
    __half2 h2; h2.x = hx; h2.y = hy;
    __half2 l2; l2.x = lx; l2.y = ly;
    hi = *(uint32_t*)&h2;
    lo = *(uint32_t*)&l2;
}
__device__ __forceinline__ void cpasync16(void* sp, const void* gp) {
    uint32_t s = (uint32_t)__cvta_generic_to_shared(sp);
    asm volatile("cp.async.cg.shared.global [%0], [%1], 16;" :: "r"(s), "l"(gp));
}
#define CP_COMMIT() asm volatile("cp.async.commit_group;")
#define CP_WAIT(n)  asm volatile("cp.async.wait_group %0;" :: "n"(n))

#define MMA_F16(d, a, b) \
  asm volatile("mma.sync.aligned.m16n8k16.row.col.f32.f16.f16.f32 " \
   "{%0,%1,%2,%3},{%4,%5,%6,%7},{%8,%9},{%0,%1,%2,%3};" \
   : "+f"((d)[0]), "+f"((d)[1]), "+f"((d)[2]), "+f"((d)[3]) \
   : "r"((a)[0]), "r"((a)[1]), "r"((a)[2]), "r"((a)[3]), "r"((b)[0]), "r"((b)[1]))

__device__ __forceinline__ void ldmA(uint32_t* r, const __half* base, int S) {
    int l = threadIdx.x & 31;
    const __half* p = (l < 16) ? (base + l * S) : (base + (l - 16) * S + 8);
    uint32_t a = (uint32_t)__cvta_generic_to_shared(p);
    asm volatile("ldmatrix.sync.aligned.m8n8.x4.shared.b16 {%0,%1,%2,%3}, [%4];"
                 : "=r"(r[0]), "=r"(r[1]), "=r"(r[2]), "=r"(r[3]) : "r"(a));
}
__device__ __forceinline__ void ldmB(uint32_t* r, const __half* base, int S) {
    int l = threadIdx.x & 31;
    int q = l >> 3, rr = l & 7;
    const __half* p = base + (rr + ((q >> 1) << 3)) * S + ((q & 1) << 3);
    uint32_t a = (uint32_t)__cvta_generic_to_shared(p);
    asm volatile("ldmatrix.sync.aligned.m8n8.x4.shared.b16 {%0,%1,%2,%3}, [%4];"
                 : "=r"(r[0]), "=r"(r[1]), "=r"(r[2]), "=r"(r[3]) : "r"(a));
}

// ---------------- CSR --------------------------------------------------------
__global__ void zero_i(int* p, int n) {
    int i = blockIdx.x * blockDim.x + threadIdx.x;
    if (i < n) p[i] = 0;
}
__global__ void zero_f(float* p, int n) {
    int i = blockIdx.x * blockDim.x + threadIdx.x;
    int stride = gridDim.x * blockDim.x;
    for (; i < n; i += stride) p[i] = 0.f;
}
__global__ void count_deg(const int* __restrict__ ei) {
    int e = blockIdx.x * blockDim.x + threadIdx.x;
    if (e < EE_) atomicAdd(&g_degi[ei[EE_ + e]], 1);
}
__global__ __launch_bounds__(1024) void scan_offsets() {
    __shared__ int s[1024];
    int t = threadIdx.x;
    int base = t * 4;
    int lp[4];
    int sum = 0;
    #pragma unroll
    for (int i = 0; i < 4; i++) { int v = g_degi[base + i]; lp[i] = sum; sum += v; }
    s[t] = sum;
    __syncthreads();
    for (int off = 1; off < 1024; off <<= 1) {
        int x = (t >= off) ? s[t - off] : 0;
        __syncthreads();
        s[t] += x;
        __syncthreads();
    }
    int excl = (t > 0) ? s[t - 1] : 0;
    #pragma unroll
    for (int i = 0; i < 4; i++) {
        int o = excl + lp[i];
        g_off[base + i] = o;
        g_cur[base + i] = o;
    }
    if (t == 1023) g_off[NN_] = s[1023];
}
__global__ void csr_fill(const int* __restrict__ ei) {
    int e = blockIdx.x * blockDim.x + threadIdx.x;
    if (e >= EE_) return;
    int d = ei[EE_ + e];
    int pos = atomicAdd(&g_cur[d], 1);
    g_csr[pos] = ei[e];
}

// ---------------- fp16 gather-mean ---------------------------------------------
__global__ __launch_bounds__(64) void gather_mean_h(const __half* __restrict__ feat,
                                                    __half* __restrict__ mean) {
    int node = blockIdx.x;
    int t = threadIdx.x;
    int beg = g_off[node], end = g_off[node + 1];
    float acc[8];
    #pragma unroll
    for (int i = 0; i < 8; i++) acc[i] = 0.f;
    for (int e = beg; e < end; ++e) {
        int s0 = __ldg(&g_csr[e]);
        uint4 v = *(const uint4*)(feat + (size_t)s0 * KP500 + t * 8);
        const __half2* h2 = (const __half2*)&v;
        #pragma unroll
        for (int i = 0; i < 4; i++) {
            float2 f = __half22float2(h2[i]);
            acc[2 * i]     += f.x;
            acc[2 * i + 1] += f.y;
        }
    }
    float inv = 1.0f / fmaxf((float)(end - beg), 1.0f);
    uint4 o;
    __half2* oh = (__half2*)&o;
    #pragma unroll
    for (int i = 0; i < 4; i++)
        oh[i] = __floats2half2_rn(acc[2 * i] * inv, acc[2 * i + 1] * inv);
    *(uint4*)(mean + (size_t)node * KP500 + t * 8) = o;
}

// ---------------- converts -----------------------------------------------------
__global__ void convert_x(const float* __restrict__ x) {
    int idx = blockIdx.x * 256 + threadIdx.x;
    if (idx >= NN_ * KP500) return;
    int col = idx & (KP500 - 1);
    int n   = idx >> 9;
    float v = (col < IN_) ? x[(size_t)n * IN_ + col] : 0.f;
    g_xh[idx] = __float2half_rn(v);
}

// ---------------- fused weight split --------------------------------------------
__device__ __forceinline__ void split_elem(const float* __restrict__ W,
                                           __half* __restrict__ hi,
                                           __half* __restrict__ lo,
                                           int Kr, int Kpad, long long local) {
    int k = (int)(local % Kpad);
    long long n = local / Kpad;
    float v = (k < Kr) ? W[n * Kr + k] : 0.f;
    splitf_h(v, hi[local], lo[local]);
}
#define SW_S0 (HH_ * KP500)
#define SW_S1 (2 * HH_ * KP500)
#define SW_S2 (SW_S1 + 3 * HH_ * KP500)
#define SW_S3 (SW_S2 + HH_ * KP500)
#define SW_S4 (SW_S3 + OUT_ * KP500)
#define SW_S5 (SW_S4 + OUT_ * KP500)
#define SW_TOTAL (SW_S5 + (long long)CC_ * 128)

__global__ void split_all(const float* __restrict__ W1s, const float* __restrict__ W1n,
                          const float* __restrict__ Win, const float* __restrict__ Wo,
                          const float* __restrict__ W2s, const float* __restrict__ W2n,
                          const float* __restrict__ Wc) {
    long long idx = (long long)blockIdx.x * 256 + threadIdx.x;
    if (idx < SW_S0)      split_elem(W1s, g_w1sh, g_w1sl, IN_, KP500, idx);
    else if (idx < SW_S1) split_elem(W1n, g_w1nh, g_w1nl, IN_, KP500, idx - SW_S0);
    else if (idx < SW_S2) split_elem(Win, g_winh, g_winl, HH_, KP500, idx - SW_S1);
    else if (idx < SW_S3) split_elem(Wo,  g_woh,  g_wol,  HH_, KP500, idx - SW_S2);
    else if (idx < SW_S4) split_elem(W2s, g_w2sh, g_w2sl, HH_, KP500, idx - SW_S3);
    else if (idx < SW_S5) split_elem(W2n, g_w2nh, g_w2nl, HH_, KP500, idx - SW_S4);
    else if (idx < SW_TOTAL) split_elem(Wc, g_wch, g_wcl, OUT_, 128, idx - SW_S5);
}

__global__ void bias_relu2(const float* __restrict__ in, const float* __restrict__ b,
                           float* __restrict__ outf) {
    int idx = blockIdx.x * 256 + threadIdx.x;
    if (idx >= NN_ * 128) return;
    int col = idx & 127;
    int n   = idx >> 7;
    float v = 0.f;
    if (col < OUT_) {
        v = fmaxf(in[(size_t)n * OUT_ + col] + b[col], 0.f);
        outf[(size_t)n * OUT_ + col] = v;
    }
    g_outxh[idx] = __float2half_rn(v);
}

// ---------------- flash attention (QK 3-pass; softmax/PV chunk-interleaved) ----
#define FQS (128 * 136)
#define FKS (64 * 136)
#define FVS (128 * 72)
#define FLASH_SMEM ((2 * FQS + 4 * FKS + 2 * FVS) * 2)

__global__ __launch_bounds__(256)
void flash_attn(const __half* __restrict__ qh, const __half* __restrict__ ql,
                const __half* __restrict__ kh, const __half* __restrict__ kl,
                const __half* __restrict__ vt,
                __half* __restrict__ attno) {
    extern __shared__ __half sm[];
    __half* sQh = sm;
    __half* sQl = sm + FQS;
    __half* sKb = sm + 2 * FQS;
    __half* sVb = sm + 2 * FQS + 4 * FKS;

    const int tid  = threadIdx.x;
    const int lane = tid & 31;
    const int wid  = tid >> 5;
    const int g    = lane >> 2;
    const int c    = lane & 3;
    const int bm   = blockIdx.x * 128;
    const int h    = blockIdx.y;

    const __half* qhp = qh + ((size_t)h * NN_ + bm) * HDP_;
    const __half* qlp = ql + ((size_t)h * NN_ + bm) * HDP_;
    const __half* khp = kh + (size_t)h * NN_ * HDP_;
    const __half* klp = kl + (size_t)h * NN_ * HDP_;
    const __half* vp  = vt + (size_t)h * HDP_ * NN_;

    #pragma unroll
    for (int i = 0; i < 16; i++) {
        int idx = tid + i * 256;
        int hf  = idx >> 11;
        int rem = idx & 2047;
        int row = rem >> 4;
        int ch  = rem & 15;
        const __half* src = (hf ? qlp : qhp) + (size_t)row * HDP_ + ch * 8;
        cpasync16((hf ? sQl : sQh) + row * 136 + ch * 8, src);
    }

    auto kvload = [&](int j, int buf) {
        __half* kb = sKb + buf * 2 * FKS;
        __half* vb = sVb + buf * FVS;
        const int key0 = j * 64;
        #pragma unroll
        for (int i = 0; i < 8; i++) {
            int idx = tid + i * 256;
            int hf  = idx >> 10;
            int rem = idx & 1023;
            int row = rem >> 4;
            int ch  = rem & 15;
            const __half* src = (hf ? klp : khp) + (size_t)(key0 + row) * HDP_ + ch * 8;
            cpasync16(kb + hf * FKS + row * 136 + ch * 8, src);
        }
        #pragma unroll
        for (int i = 0; i < 4; i++) {
            int idx = tid + i * 256;
            int row = idx >> 3;
            int ch  = idx & 7;
            const __half* src = vp + (size_t)row * NN_ + key0 + ch * 8;
            cpasync16(vb + row * 72 + ch * 8, src);
        }
    };

    kvload(0, 0);
    CP_COMMIT();

    float m0 = -1e30f, m1 = -1e30f, l0 = 0.f, l1 = 0.f;
    float acco[16][4];
    #pragma unroll
    for (int i = 0; i < 16; i++)
        #pragma unroll
        for (int q = 0; q < 4; q++) acco[i][q] = 0.f;

    const int arow = wid * 16 + g;

    for (int j = 0; j < NKT; ++j) {
        if (j + 1 < NKT) {
            kvload(j + 1, (j + 1) & 1);
            CP_COMMIT();
            CP_WAIT(1);
        } else {
            CP_WAIT(0);
        }
        __syncthreads();

        const __half* kbh = sKb + (j & 1) * 2 * FKS;
        const __half* kbl = kbh + FKS;
        const __half* vb  = sVb + (j & 1) * FVS;

        float accs[8][4];
        #pragma unroll
        for (int i = 0; i < 8; i++)
            #pragma unroll
            for (int q = 0; q < 4; q++) accs[i][q] = 0.f;

        // ---- S = Q @ K^T (3-pass fp16 hi/lo) ----
        #pragma unroll
        for (int ks = 0; ks < 8; ++ks) {
            uint32_t ahh[4], alo[4];
            ldmA(ahh, sQh + (wid * 16) * 136 + ks * 16, 136);
            ldmA(alo, sQl + (wid * 16) * 136 + ks * 16, 136);
            #pragma unroll
            for (int ntp = 0; ntp < 4; ++ntp) {
                uint32_t bh4[4], bl4[4];
                ldmB(bh4, kbh + (ntp * 16) * 136 + ks * 16, 136);
                ldmB(bl4, kbl + (ntp * 16) * 136 + ks * 16, 136);
                #pragma unroll
                for (int half = 0; half < 2; ++half) {
                    uint32_t bh[2] = {bh4[half * 2], bh4[half * 2 + 1]};
                    uint32_t bl[2] = {bl4[half * 2], bl4[half * 2 + 1]};
                    int nt = ntp * 2 + half;
                    MMA_F16(accs[nt], ahh, bh);
                    MMA_F16(accs[nt], ahh, bl);
                    MMA_F16(accs[nt], alo, bh);
                }
            }
        }

        // ---- max reduce + rescale ----
        float t0 = -1e30f, t1 = -1e30f;
        #pragma unroll
        for (int nt = 0; nt < 8; ++nt) {
            t0 = fmaxf(t0, fmaxf(accs[nt][0], accs[nt][1]));
            t1 = fmaxf(t1, fmaxf(accs[nt][2], accs[nt][3]));
        }
        t0 = fmaxf(t0, __shfl_xor_sync(0xffffffffu, t0, 1));
        t0 = fmaxf(t0, __shfl_xor_sync(0xffffffffu, t0, 2));
        t1 = fmaxf(t1, __shfl_xor_sync(0xffffffffu, t1, 1));
        t1 = fmaxf(t1, __shfl_xor_sync(0xffffffffu, t1, 2));
        float nm0 = fmaxf(m0, t0), nm1 = fmaxf(m1, t1);
        float sc0 = __expf(m0 - nm0), sc1 = __expf(m1 - nm1);

        #pragma unroll
        for (int nt = 0; nt < 16; ++nt) {
            acco[nt][0] *= sc0; acco[nt][1] *= sc0;
            acco[nt][2] *= sc1; acco[nt][3] *= sc1;
        }

        // ---- per-chunk: exp+split, then immediately PV mma (overlaps pipes) ----
        float ps0 = 0.f, ps1 = 0.f;
        #pragma unroll
        for (int kk = 0; kk < 4; ++kk) {
            float p00 = __expf(accs[2 * kk][0] - nm0);
            float p01 = __expf(accs[2 * kk][1] - nm0);
            float p02 = __expf(accs[2 * kk][2] - nm1);
            float p03 = __expf(accs[2 * kk][3] - nm1);
            float p10 = __expf(accs[2 * kk + 1][0] - nm0);
            float p11 = __expf(accs[2 * kk + 1][1] - nm0);
            float p12 = __expf(accs[2 * kk + 1][2] - nm1);
            float p13 = __expf(accs[2 * kk + 1][3] - nm1);
            ps0 += p00 + p01 + p10 + p11;
            ps1 += p02 + p03 + p12 + p13;
            uint32_t ph[4], pl[4];
            split2h(p00, p01, ph[0], pl[0]);
            split2h(p02, p03, ph[1], pl[1]);
            split2h(p10, p11, ph[2], pl[2]);
            split2h(p12, p13, ph[3], pl[3]);
            #pragma unroll
            for (int ntp = 0; ntp < 8; ++ntp) {
                uint32_t v4[4];
                ldmB(v4, vb + (ntp * 16) * 72 + kk * 16, 72);
                #pragma unroll
                for (int half = 0; half < 2; ++half) {
                    uint32_t bv[2] = {v4[half * 2], v4[half * 2 + 1]};
                    int nt = ntp * 2 + half;
                    MMA_F16(acco[nt], ph, bv);
                    MMA_F16(acco[nt], pl, bv);
                }
            }
        }
        ps0 += __shfl_xor_sync(0xffffffffu, ps0, 1);
        ps0 += __shfl_xor_sync(0xffffffffu, ps0, 2);
        ps1 += __shfl_xor_sync(0xffffffffu, ps1, 1);
        ps1 += __shfl_xor_sync(0xffffffffu, ps1, 2);
        l0 = l0 * sc0 + ps0;
        l1 = l1 * sc1 + ps1;
        m0 = nm0;
        m1 = nm1;
        __syncthreads();
    }

    float i0 = 1.0f / l0, i1 = 1.0f / l1;
    int r0 = bm + arow;
    #pragma unroll
    for (int nt = 0; nt < 16; ++nt) {
        int col = nt * 8 + c * 2;
        if (col < HD_) {
            attno[(size_t)r0 * KP500 + h * HD_ + col]       = __float2half_rn(acco[nt][0] * i0);
            attno[(size_t)(r0 + 8) * KP500 + h * HD_ + col] = __float2half_rn(acco[nt][2] * i1);
        }
        if (col + 1 < HD_) {
            attno[(size_t)r0 * KP500 + h * HD_ + col + 1]       = __float2half_rn(acco[nt][1] * i0);
            attno[(size_t)(r0 + 8) * KP500 + h * HD_ + col + 1] = __float2half_rn(acco[nt][3] * i1);
        }
    }
}

// ---------------- fp16 GEMM ------------------------------------------------------
// mode 0: fp32 store (+bias, opt relu); mode 1: atomicAdd fp32;
// mode 2: fp16 store, zeroed pad (+bias, opt relu);
// mode 3: qkv epilogue — split q (scaled)/k into hi/lo head arrays, V transposed.
// npassB: 1 = hi-only B, 2 = hi+lo B.
__global__ __launch_bounds__(512, 1)
void gemm_fh(const __half* __restrict__ A1, const __half* __restrict__ A2, int lda,
             const __half* __restrict__ B1h, const __half* __restrict__ B1l,
             const __half* __restrict__ B2h, const __half* __restrict__ B2l,
             int ldb,
             const float* __restrict__ bias,
             void* __restrict__ C_, int ldc,
             int Nfull, int Kpad, int relu, int mode, int ksplit,
             int npassB, float qscale) {
    __shared__ __align__(16) __half sA[128 * 40];
    __shared__ __align__(16) __half sBh[128 * 40];
    __shared__ __align__(16) __half sBl[128 * 40];

    const int tid  = threadIdx.x;
    const int lane = tid & 31;
    const int wid  = tid >> 5;
    const int wm   = wid & 3;
    const int wn   = wid >> 2;
    const int bm   = blockIdx.y * 128;
    const int bn   = blockIdx.x * 128;
    const int ks   = blockIdx.z % ksplit;
    const int klen = Kpad / ksplit;
    const int kb   = ks * klen;

    float acc[2][4][4];
    #pragma unroll
    for (int i = 0; i < 2; i++)
        #pragma unroll
        for (int j = 0; j < 4; j++)
            #pragma unroll
            for (int q = 0; q < 4; q++) acc[i][j][q] = 0.f;

    const int npairs = (A2 != nullptr) ? 2 : 1;
    const int r  = tid >> 2;
    const int gq = tid & 3;
    const bool bok = (bn + r) < Nfull;

    for (int pr = 0; pr < npairs; ++pr) {
        const __half* A  = (pr ? A2 : A1) + kb;
        const __half* Bh = (pr ? B2h : B1h) + kb;
        const __half* Bl = (pr ? B2l : B1l) + kb;

        uint4 stA, stBh, stBl;
        auto prefetch = [&](int k0) {
            stA = *(const uint4*)(A + (size_t)(bm + r) * lda + k0 + gq * 8);
            if (bok) {
                stBh = *(const uint4*)(Bh + (size_t)(bn + r) * ldb + k0 + gq * 8);
                if (npassB > 1)
                    stBl = *(const uint4*)(Bl + (size_t)(bn + r) * ldb + k0 + gq * 8);
            } else {
                stBh = make_uint4(0, 0, 0, 0);
                stBl = make_uint4(0, 0, 0, 0);
            }
        };
        auto store_smem = [&]() {
            *(uint4*)(sA  + r * 40 + gq * 8) = stA;
            *(uint4*)(sBh + r * 40 + gq * 8) = stBh;
            if (npassB > 1) *(uint4*)(sBl + r * 40 + gq * 8) = stBl;
        };

        prefetch(0);
        for (int k0 = 0; k0 < klen; k0 += 32) {
            store_smem();
            __syncthreads();
            if (k0 + 32 < klen) prefetch(k0 + 32);

            #pragma unroll
            for (int ksf = 0; ksf < 2; ++ksf) {
                uint32_t a[2][4];
                #pragma unroll
                for (int mt = 0; mt < 2; ++mt)
                    ldmA(a[mt], sA + (wm * 32 + mt * 16) * 40 + ksf * 16, 40);
                #pragma unroll
                for (int ntp = 0; ntp < 2; ++ntp) {
                    uint32_t bh4[4], bl4[4];
                    ldmB(bh4, sBh + (wn * 32 + ntp * 16) * 40 + ksf * 16, 40);
                    if (npassB > 1)
                        ldmB(bl4, sBl + (wn * 32 + ntp * 16) * 40 + ksf * 16, 40);
                    #pragma unroll
                    for (int half = 0; half < 2; ++half) {
                        uint32_t bh[2] = {bh4[half * 2], bh4[half * 2 + 1]};
                        int nt = ntp * 2 + half;
                        #pragma unroll
                        for (int mt = 0; mt < 2; ++mt)
                            MMA_F16(acc[mt][nt], a[mt], bh);
                        if (npassB > 1) {
                            uint32_t bl[2] = {bl4[half * 2], bl4[half * 2 + 1]};
                            #pragma unroll
                            for (int mt = 0; mt < 2; ++mt)
                                MMA_F16(acc[mt][nt], a[mt], bl);
                        }
                    }
                }
            }
            __syncthreads();
        }
    }

    if (mode == 0) {
        float* C = (float*)C_;
        #pragma unroll
        for (int mt = 0; mt < 2; ++mt) {
            int row = bm + wm * 32 + mt * 16 + (lane >> 2);
            #pragma unroll
            for (int nt = 0; nt < 4; ++nt) {
                int gc = bn + wn * 32 + nt * 8 + ((lane & 3) << 1);
                #pragma unroll
                for (int j = 0; j < 2; ++j) {
                    if (gc + j < Nfull) {
                        float bsv = bias ? bias[gc + j] : 0.f;
                        float v0 = acc[mt][nt][j] + bsv;
                        float v1 = acc[mt][nt][j + 2] + bsv;
                        if (relu) { v0 = fmaxf(v0, 0.f); v1 = fmaxf(v1, 0.f); }
                        C[(size_t)row * ldc + gc + j] = v0;
                        C[(size_t)(row + 8) * ldc + gc + j] = v1;
                    }
                }
            }
        }
    } else if (mode == 1) {
        float* C = (float*)C_;
        #pragma unroll
        for (int mt = 0; mt < 2; ++mt) {
            int row = bm + wm * 32 + mt * 16 + (lane >> 2);
            #pragma unroll
            for (int nt = 0; nt < 4; ++nt) {
                int gc = bn + wn * 32 + nt * 8 + ((lane & 3) << 1);
                #pragma unroll
                for (int j = 0; j < 2; ++j) {
                    if (gc + j < Nfull) {
                        atomicAdd(&C[(size_t)row * ldc + gc + j], acc[mt][nt][j]);
                        atomicAdd(&C[(size_t)(row + 8) * ldc + gc + j], acc[mt][nt][j + 2]);
                    }
                }
            }
        }
    } else if (mode == 2) {
        __half* C = (__half*)C_;
        #pragma unroll
        for (int mt = 0; mt < 2; ++mt) {
            int row = bm + wm * 32 + mt * 16 + (lane >> 2);
            #pragma unroll
            for (int nt = 0; nt < 4; ++nt) {
                int gc = bn + wn * 32 + nt * 8 + ((lane & 3) << 1);
                #pragma unroll
                for (int j = 0; j < 2; ++j) {
                    float v0 = 0.f, v1 = 0.f;
                    if (gc + j < Nfull) {
                        float bsv = bias ? bias[gc + j] : 0.f;
                        v0 = acc[mt][nt][j] + bsv;
                        v1 = acc[mt][nt][j + 2] + bsv;
                        if (relu) { v0 = fmaxf(v0, 0.f); v1 = fmaxf(v1, 0.f); }
                    }
                    C[(size_t)row * ldc + gc + j] = __float2half_rn(v0);
                    C[(size_t)(row + 8) * ldc + gc + j] = __float2half_rn(v1);
                }
            }
        }
    } else {
        // mode 3: qkv split epilogue (bias = b_in, Nfull = 1500)
        #pragma unroll
        for (int mt = 0; mt < 2; ++mt) {
            int n0 = bm + wm * 32 + mt * 16 + (lane >> 2);
            int n1 = n0 + 8;
            #pragma unroll
            for (int nt = 0; nt < 4; ++nt) {
                int gc = bn + wn * 32 + nt * 8 + ((lane & 3) << 1);
                #pragma unroll
                for (int j = 0; j < 2; ++j) {
                    int cc = gc + j;
                    if (cc >= 3 * HH_) continue;
                    float v0 = acc[mt][nt][j]     + bias[cc];
                    float v1 = acc[mt][nt][j + 2] + bias[cc];
                    if (cc < HH_) {
                        int h = cc / HD_;
                        int d = cc - h * HD_;
                        size_t b0 = ((size_t)h * NN_ + n0) * HDP_ + d;
                        size_t b1 = ((size_t)h * NN_ + n1) * HDP_ + d;
                        __half hh, ll;
                        splitf_h(v0 * qscale, hh, ll);
                        g_qh[b0] = hh; g_ql[b0] = ll;
                        splitf_h(v1 * qscale, hh, ll);
                        g_qh[b1] = hh; g_ql[b1] = ll;
                    } else if (cc < 2 * HH_) {
                        int c2 = cc - HH_;
                        int h = c2 / HD_;
                        int d = c2 - h * HD_;
                        size_t b0 = ((size_t)h * NN_ + n0) * HDP_ + d;
                        size_t b1 = ((size_t)h * NN_ + n1) * HDP_ + d;
                        __half hh, ll;
                        splitf_h(v0, hh, ll);
                        g_kh[b0] = hh; g_kl[b0] = ll;
                        splitf_h(v1, hh, ll);
                        g_kh[b1] = hh; g_kl[b1] = ll;
                    } else {
                        int c2 = cc - 2 * HH_;
                        int h = c2 / HD_;
                        int d = c2 - h * HD_;
                        size_t base = ((size_t)h * HDP_ + d) * NN_;
                        g_vt[base + n0] = __float2half_rn(v0);
                        g_vt[base + n1] = __float2half_rn(v1);
                    }
                }
            }
        }
    }
}

// ---------------- launch -----------------------------------------------------
extern "C" void kernel_launch(void* const* d_in, const int* in_sizes, int n_in,
                              void* d_out, int out_size) {
    const float* x        = (const float*)d_in[0];
    const int*   ei       = (const int*)d_in[1];
    const float* W1_self  = (const float*)d_in[2];
    const float* W1_neigh = (const float*)d_in[3];
    const float* b1       = (const float*)d_in[4];
    const float* W_in     = (const float*)d_in[5];
    const float* b_in     = (const float*)d_in[6];
    const float* W_out    = (const float*)d_in[7];
    const float* b_out    = (const float*)d_in[8];
    const float* W2_self  = (const float*)d_in[9];
    const float* W2_neigh = (const float*)d_in[10];
    const float* b2       = (const float*)d_in[11];
    const float* Wc       = (const float*)d_in[12];
    const float* bc       = (const float*)d_in[13];

    float* out_x      = (float*)d_out;
    float* out_logits = (float*)d_out + (size_t)NN_ * OUT_;

    int* degi;
    float* tmp2;
    __half *xh, *meanh, *h1h, *attnoh, *h2h, *outxh;
    cudaGetSymbolAddress((void**)&degi,   g_degi);
    cudaGetSymbolAddress((void**)&xh,     g_xh);
    cudaGetSymbolAddress((void**)&meanh,  g_meanh);
    cudaGetSymbolAddress((void**)&h1h,    g_h1h);
    cudaGetSymbolAddress((void**)&attnoh, g_attnoh);
    cudaGetSymbolAddress((void**)&h2h,    g_h2h);
    cudaGetSymbolAddress((void**)&tmp2,   g_tmp2);
    cudaGetSymbolAddress((void**)&outxh,  g_outxh);

    __half *qh, *ql, *kh, *kl, *vt;
    __half *w1sh, *w1sl, *w1nh, *w1nl, *winh, *winl, *woh, *wol;
    __half *w2sh, *w2sl, *w2nh, *w2nl, *wch, *wcl;
    cudaGetSymbolAddress((void**)&qh,   g_qh);
    cudaGetSymbolAddress((void**)&ql,   g_ql);
    cudaGetSymbolAddress((void**)&kh,   g_kh);
    cudaGetSymbolAddress((void**)&kl,   g_kl);
    cudaGetSymbolAddress((void**)&vt,   g_vt);
    cudaGetSymbolAddress((void**)&w1sh, g_w1sh); cudaGetSymbolAddress((void**)&w1sl, g_w1sl);
    cudaGetSymbolAddress((void**)&w1nh, g_w1nh); cudaGetSymbolAddress((void**)&w1nl, g_w1nl);
    cudaGetSymbolAddress((void**)&winh, g_winh); cudaGetSymbolAddress((void**)&winl, g_winl);
    cudaGetSymbolAddress((void**)&woh,  g_woh);  cudaGetSymbolAddress((void**)&wol,  g_wol);
    cudaGetSymbolAddress((void**)&w2sh, g_w2sh); cudaGetSymbolAddress((void**)&w2sl, g_w2sl);
    cudaGetSymbolAddress((void**)&w2nh, g_w2nh); cudaGetSymbolAddress((void**)&w2nl, g_w2nl);
    cudaGetSymbolAddress((void**)&wch,  g_wch);  cudaGetSymbolAddress((void**)&wcl,  g_wcl);

    cudaFuncSetAttribute(flash_attn, cudaFuncAttributeMaxDynamicSharedMemorySize, FLASH_SMEM);

    const float scale = 1.0f / sqrtf((float)HD_);

    // ---- CSR build ----
    zero_i<<<16, 256>>>(degi, NN_);
    count_deg<<<EE_ / 256, 256>>>(ei);
    scan_offsets<<<1, 1024>>>();
    csr_fill<<<EE_ / 256, 256>>>(ei);

    // ---- weight pre-splits + x convert ----
    split_all<<<(unsigned)((SW_TOTAL + 255) / 256), 256>>>(W1_self, W1_neigh, W_in,
                                                           W_out, W2_self, W2_neigh, Wc);
    convert_x<<<(NN_ * KP500 + 255) / 256, 256>>>(x);

    // ---- SAGE 1 (fp16 out) ----
    gather_mean_h<<<NN_, 64>>>(xh, meanh);
    {
        dim3 grid(4, 32, 1);
        gemm_fh<<<grid, 512>>>(xh, meanh, KP500, w1sh, w1sl, w1nh, w1nl, KP500,
                               b1, h1h, KP500, HH_, KP500, 1, 2, 1, 2, 0.f);
    }

    // ---- qkv projection with fused q/k/v split epilogue ----
    {
        dim3 grid(12, 32, 1);
        gemm_fh<<<grid, 512>>>(h1h, nullptr, KP500, winh, winl, nullptr, nullptr, KP500,
                               b_in, nullptr, 0, 3 * HH_, KP500, 0, 3, 1, 2, scale);
    }

    // ---- flash attention (fp16 out; pads persist zero) ----
    {
        dim3 grid(NN_ / 128, NHEAD);
        flash_attn<<<grid, 256, FLASH_SMEM>>>(qh, ql, kh, kl, vt, attnoh);
    }

    // ---- out projection (fp16 out) ----
    {
        dim3 grid(4, 32, 1);
        gemm_fh<<<grid, 512>>>(attnoh, nullptr, KP500, woh, wol, nullptr, nullptr, KP500,
                               b_out, h2h, KP500, HH_, KP500, 1, 2, 1, 2, 0.f);
    }

    // ---- SAGE 2 (split-K=4 atomic fp32, then bias+relu dual-write) ----
    gather_mean_h<<<NN_, 64>>>(h2h, meanh);
    zero_f<<<1600, 256>>>(tmp2, NN_ * OUT_);
    {
        dim3 grid(1, 32, 4);
        gemm_fh<<<grid, 512>>>(h2h, meanh, KP500, w2sh, w2sl, w2nh, w2nl, KP500,
                               nullptr, tmp2, OUT_, OUT_, KP500, 0, 1, 4, 2, 0.f);
    }
    bias_relu2<<<(NN_ * 128 + 255) / 256, 256>>>(tmp2, b2, out_x);

    // ---- classifier (single-pass fp16: hi weights only) ----
    {
        dim3 grid(CCP_ / 128, 32, 1);
        gemm_fh<<<grid, 512>>>(outxh, nullptr, 128, wch, wcl, nullptr, nullptr, 128,
                               bc, out_logits, CC_, CC_, 128, 0, 0, 1, 1, 0.f);
    }
}

// round 15
// speedup vs baseline: 1.0176x; 1.0176x over previous
#include <cuda_runtime.h>
#include <cuda_fp16.h>
#include <math.h>
#include <stdint.h>

#define NN_   4096
#define EE_   131072
#define IN_   500
#define HH_   500
#define OUT_  100
#define CC_   15451
#define CCP_  15488
#define NHEAD 4
#define HD_   125
#define HDP_  128
#define KP500 512
#define NKT   (NN_ / 64)

// ---------------- scratch ----------------------------------------------------
__device__ int    g_degi[NN_];     // zero at every call entry (scan resets it)
__device__ int    g_off[NN_ + 1];
__device__ int    g_cur[NN_];
__device__ int    g_csr[EE_];
__device__ __half g_xh[NN_ * KP500];
__device__ __half g_meanh[NN_ * KP500];
__device__ __half g_h1h[NN_ * KP500];
__device__ __half g_attnoh[NN_ * KP500];   // pads stay zero forever
__device__ __half g_h2h[NN_ * KP500];
__device__ float  g_tmp2[NN_ * OUT_];
__device__ __half g_outxh[NN_ * 128];

__device__ __half g_qh[NHEAD * NN_ * HDP_];
__device__ __half g_ql[NHEAD * NN_ * HDP_];
__device__ __half g_kh[NHEAD * NN_ * HDP_];
__device__ __half g_kl[NHEAD * NN_ * HDP_];
__device__ __half g_vt[NHEAD * HDP_ * NN_];

__device__ __half g_w1sh[HH_ * KP500], g_w1sl[HH_ * KP500];
__device__ __half g_w1nh[HH_ * KP500], g_w1nl[HH_ * KP500];
__device__ __half g_winh[3 * HH_ * KP500], g_winl[3 * HH_ * KP500];
__device__ __half g_woh[HH_ * KP500], g_wol[HH_ * KP500];
__device__ __half g_w2sh[OUT_ * KP500], g_w2sl[OUT_ * KP500];
__device__ __half g_w2nh[OUT_ * KP500], g_w2nl[OUT_ * KP500];
__device__ __half g_wch[(size_t)CC_ * 128], g_wcl[(size_t)CC_ * 128];

// ---------------- helpers ----------------------------------------------------
__device__ __forceinline__ void splitf_h(float x, __half& h, __half& l) {
    h = __float2half_rn(x);
    l = __float2half_rn(x - __half2float(h));
}
__device__ __forceinline__ void split2h(float x, float y, uint32_t& hi, uint32_t& lo) {
    __half hx = __float2half_rn(x), hy = __float2half_rn(y);
    __half lx = __float2half_rn(x - __half2float(hx));
    __half ly = __float2half_rn(y - __half2float(hy));
    __half2 h2; h2.x = hx; h2.y = hy;
    __half2 l2; l2.x = lx; l2.y = ly;
    hi = *(uint32_t*)&h2;
    lo = *(uint32_t*)&l2;
}
__device__ __forceinline__ void cpasync16(void* sp, const void* gp) {
    uint32_t s = (uint32_t)__cvta_generic_to_shared(sp);
    asm volatile("cp.async.cg.shared.global [%0], [%1], 16;" :: "r"(s), "l"(gp));
}
#define CP_COMMIT() asm volatile("cp.async.commit_group;")
#define CP_WAIT(n)  asm volatile("cp.async.wait_group %0;" :: "n"(n))

#define MMA_F16(d, a, b) \
  asm volatile("mma.sync.aligned.m16n8k16.row.col.f32.f16.f16.f32 " \
   "{%0,%1,%2,%3},{%4,%5,%6,%7},{%8,%9},{%0,%1,%2,%3};" \
   : "+f"((d)[0]), "+f"((d)[1]), "+f"((d)[2]), "+f"((d)[3]) \
   : "r"((a)[0]), "r"((a)[1]), "r"((a)[2]), "r"((a)[3]), "r"((b)[0]), "r"((b)[1]))

__device__ __forceinline__ void ldmA(uint32_t* r, const __half* base, int S) {
    int l = threadIdx.x & 31;
    const __half* p = (l < 16) ? (base + l * S) : (base + (l - 16) * S + 8);
    uint32_t a = (uint32_t)__cvta_generic_to_shared(p);
    asm volatile("ldmatrix.sync.aligned.m8n8.x4.shared.b16 {%0,%1,%2,%3}, [%4];"
                 : "=r"(r[0]), "=r"(r[1]), "=r"(r[2]), "=r"(r[3]) : "r"(a));
}
__device__ __forceinline__ void ldmB(uint32_t* r, const __half* base, int S) {
    int l = threadIdx.x & 31;
    int q = l >> 3, rr = l & 7;
    const __half* p = base + (rr + ((q >> 1) << 3)) * S + ((q & 1) << 3);
    uint32_t a = (uint32_t)__cvta_generic_to_shared(p);
    asm volatile("ldmatrix.sync.aligned.m8n8.x4.shared.b16 {%0,%1,%2,%3}, [%4];"
                 : "=r"(r[0]), "=r"(r[1]), "=r"(r[2]), "=r"(r[3]) : "r"(a));
}

// ---------------- CSR --------------------------------------------------------
__global__ void count_deg(const int* __restrict__ ei) {
    int e = blockIdx.x * blockDim.x + threadIdx.x;
    if (e < EE_) atomicAdd(&g_degi[ei[EE_ + e]], 1);
}
__global__ __launch_bounds__(1024) void scan_offsets() {
    __shared__ int s[1024];
    int t = threadIdx.x;
    int base = t * 4;
    int lp[4];
    int sum = 0;
    #pragma unroll
    for (int i = 0; i < 4; i++) {
        int v = g_degi[base + i];
        g_degi[base + i] = 0;          // reset for next call (state invariant: zero at entry)
        lp[i] = sum; sum += v;
    }
    s[t] = sum;
    __syncthreads();
    for (int off = 1; off < 1024; off <<= 1) {
        int x = (t >= off) ? s[t - off] : 0;
        __syncthreads();
        s[t] += x;
        __syncthreads();
    }
    int excl = (t > 0) ? s[t - 1] : 0;
    #pragma unroll
    for (int i = 0; i < 4; i++) {
        int o = excl + lp[i];
        g_off[base + i] = o;
        g_cur[base + i] = o;
    }
    if (t == 1023) g_off[NN_] = s[1023];
}
__global__ void csr_fill(const int* __restrict__ ei) {
    int e = blockIdx.x * blockDim.x + threadIdx.x;
    if (e >= EE_) return;
    int d = ei[EE_ + e];
    int pos = atomicAdd(&g_cur[d], 1);
    g_csr[pos] = ei[e];
}

// ---------------- fp16 gather-mean ---------------------------------------------
__global__ __launch_bounds__(64) void gather_mean_h(const __half* __restrict__ feat,
                                                    __half* __restrict__ mean) {
    int node = blockIdx.x;
    int t = threadIdx.x;
    int beg = g_off[node], end = g_off[node + 1];
    float acc[8];
    #pragma unroll
    for (int i = 0; i < 8; i++) acc[i] = 0.f;
    for (int e = beg; e < end; ++e) {
        int s0 = __ldg(&g_csr[e]);
        uint4 v = *(const uint4*)(feat + (size_t)s0 * KP500 + t * 8);
        const __half2* h2 = (const __half2*)&v;
        #pragma unroll
        for (int i = 0; i < 4; i++) {
            float2 f = __half22float2(h2[i]);
            acc[2 * i]     += f.x;
            acc[2 * i + 1] += f.y;
        }
    }
    float inv = 1.0f / fmaxf((float)(end - beg), 1.0f);
    uint4 o;
    __half2* oh = (__half2*)&o;
    #pragma unroll
    for (int i = 0; i < 4; i++)
        oh[i] = __floats2half2_rn(acc[2 * i] * inv, acc[2 * i + 1] * inv);
    *(uint4*)(mean + (size_t)node * KP500 + t * 8) = o;
}

// ---------------- fused prep: weight splits + x convert + tmp2 zero -------------
__device__ __forceinline__ void split_elem(const float* __restrict__ W,
                                           __half* __restrict__ hi,
                                           __half* __restrict__ lo,
                                           int Kr, int Kpad, long long local) {
    int k = (int)(local % Kpad);
    long long n = local / Kpad;
    float v = (k < Kr) ? W[n * Kr + k] : 0.f;
    splitf_h(v, hi[local], lo[local]);
}
#define SW_S0 (HH_ * KP500)
#define SW_S1 (2 * HH_ * KP500)
#define SW_S2 (SW_S1 + 3 * HH_ * KP500)
#define SW_S3 (SW_S2 + HH_ * KP500)
#define SW_S4 (SW_S3 + OUT_ * KP500)
#define SW_S5 (SW_S4 + OUT_ * KP500)
#define SW_S6 (SW_S5 + (long long)CC_ * 128)
#define SW_S7 (SW_S6 + NN_ * KP500)                 // convert_x range
#define SW_TOTAL (SW_S7 + NN_ * OUT_)               // tmp2 zero range

__global__ void prep_all(const float* __restrict__ W1s, const float* __restrict__ W1n,
                         const float* __restrict__ Win, const float* __restrict__ Wo,
                         const float* __restrict__ W2s, const float* __restrict__ W2n,
                         const float* __restrict__ Wc, const float* __restrict__ x) {
    long long idx = (long long)blockIdx.x * 256 + threadIdx.x;
    if (idx < SW_S0)      split_elem(W1s, g_w1sh, g_w1sl, IN_, KP500, idx);
    else if (idx < SW_S1) split_elem(W1n, g_w1nh, g_w1nl, IN_, KP500, idx - SW_S0);
    else if (idx < SW_S2) split_elem(Win, g_winh, g_winl, HH_, KP500, idx - SW_S1);
    else if (idx < SW_S3) split_elem(Wo,  g_woh,  g_wol,  HH_, KP500, idx - SW_S2);
    else if (idx < SW_S4) split_elem(W2s, g_w2sh, g_w2sl, HH_, KP500, idx - SW_S3);
    else if (idx < SW_S5) split_elem(W2n, g_w2nh, g_w2nl, HH_, KP500, idx - SW_S4);
    else if (idx < SW_S6) split_elem(Wc,  g_wch,  g_wcl,  OUT_, 128, idx - SW_S5);
    else if (idx < SW_S7) {
        long long j = idx - SW_S6;
        int col = (int)(j & (KP500 - 1));
        int n   = (int)(j >> 9);
        float v = (col < IN_) ? x[(size_t)n * IN_ + col] : 0.f;
        g_xh[j] = __float2half_rn(v);
    } else if (idx < SW_TOTAL) {
        g_tmp2[idx - SW_S7] = 0.f;
    }
}

__global__ void bias_relu2(const float* __restrict__ in, const float* __restrict__ b,
                           float* __restrict__ outf) {
    int idx = blockIdx.x * 256 + threadIdx.x;
    if (idx >= NN_ * 128) return;
    int col = idx & 127;
    int n   = idx >> 7;
    float v = 0.f;
    if (col < OUT_) {
        v = fmaxf(in[(size_t)n * OUT_ + col] + b[col], 0.f);
        outf[(size_t)n * OUT_ + col] = v;
    }
    g_outxh[idx] = __float2half_rn(v);
}

// ---------------- flash attention (R13 form) ------------------------------------
#define FQS (128 * 136)
#define FKS (64 * 136)
#define FVS (128 * 72)
#define FLASH_SMEM ((2 * FQS + 4 * FKS + 2 * FVS) * 2)

__global__ __launch_bounds__(256)
void flash_attn(const __half* __restrict__ qh, const __half* __restrict__ ql,
                const __half* __restrict__ kh, const __half* __restrict__ kl,
                const __half* __restrict__ vt,
                __half* __restrict__ attno) {
    extern __shared__ __half sm[];
    __half* sQh = sm;
    __half* sQl = sm + FQS;
    __half* sKb = sm + 2 * FQS;
    __half* sVb = sm + 2 * FQS + 4 * FKS;

    const int tid  = threadIdx.x;
    const int lane = tid & 31;
    const int wid  = tid >> 5;
    const int g    = lane >> 2;
    const int c    = lane & 3;
    const int bm   = blockIdx.x * 128;
    const int h    = blockIdx.y;

    const __half* qhp = qh + ((size_t)h * NN_ + bm) * HDP_;
    const __half* qlp = ql + ((size_t)h * NN_ + bm) * HDP_;
    const __half* khp = kh + (size_t)h * NN_ * HDP_;
    const __half* klp = kl + (size_t)h * NN_ * HDP_;
    const __half* vp  = vt + (size_t)h * HDP_ * NN_;

    #pragma unroll
    for (int i = 0; i < 16; i++) {
        int idx = tid + i * 256;
        int hf  = idx >> 11;
        int rem = idx & 2047;
        int row = rem >> 4;
        int ch  = rem & 15;
        const __half* src = (hf ? qlp : qhp) + (size_t)row * HDP_ + ch * 8;
        cpasync16((hf ? sQl : sQh) + row * 136 + ch * 8, src);
    }

    auto kvload = [&](int j, int buf) {
        __half* kb = sKb + buf * 2 * FKS;
        __half* vb = sVb + buf * FVS;
        const int key0 = j * 64;
        #pragma unroll
        for (int i = 0; i < 8; i++) {
            int idx = tid + i * 256;
            int hf  = idx >> 10;
            int rem = idx & 1023;
            int row = rem >> 4;
            int ch  = rem & 15;
            const __half* src = (hf ? klp : khp) + (size_t)(key0 + row) * HDP_ + ch * 8;
            cpasync16(kb + hf * FKS + row * 136 + ch * 8, src);
        }
        #pragma unroll
        for (int i = 0; i < 4; i++) {
            int idx = tid + i * 256;
            int row = idx >> 3;
            int ch  = idx & 7;
            const __half* src = vp + (size_t)row * NN_ + key0 + ch * 8;
            cpasync16(vb + row * 72 + ch * 8, src);
        }
    };

    kvload(0, 0);
    CP_COMMIT();

    float m0 = -1e30f, m1 = -1e30f, l0 = 0.f, l1 = 0.f;
    float acco[16][4];
    #pragma unroll
    for (int i = 0; i < 16; i++)
        #pragma unroll
        for (int q = 0; q < 4; q++) acco[i][q] = 0.f;

    const int arow = wid * 16 + g;

    for (int j = 0; j < NKT; ++j) {
        if (j + 1 < NKT) {
            kvload(j + 1, (j + 1) & 1);
            CP_COMMIT();
            CP_WAIT(1);
        } else {
            CP_WAIT(0);
        }
        __syncthreads();

        const __half* kbh = sKb + (j & 1) * 2 * FKS;
        const __half* kbl = kbh + FKS;
        const __half* vb  = sVb + (j & 1) * FVS;

        float accs[8][4];
        #pragma unroll
        for (int i = 0; i < 8; i++)
            #pragma unroll
            for (int q = 0; q < 4; q++) accs[i][q] = 0.f;

        #pragma unroll
        for (int ks = 0; ks < 8; ++ks) {
            uint32_t ahh[4], alo[4];
            ldmA(ahh, sQh + (wid * 16) * 136 + ks * 16, 136);
            ldmA(alo, sQl + (wid * 16) * 136 + ks * 16, 136);
            #pragma unroll
            for (int ntp = 0; ntp < 4; ++ntp) {
                uint32_t bh4[4], bl4[4];
                ldmB(bh4, kbh + (ntp * 16) * 136 + ks * 16, 136);
                ldmB(bl4, kbl + (ntp * 16) * 136 + ks * 16, 136);
                #pragma unroll
                for (int half = 0; half < 2; ++half) {
                    uint32_t bh[2] = {bh4[half * 2], bh4[half * 2 + 1]};
                    uint32_t bl[2] = {bl4[half * 2], bl4[half * 2 + 1]};
                    int nt = ntp * 2 + half;
                    MMA_F16(accs[nt], ahh, bh);
                    MMA_F16(accs[nt], ahh, bl);
                    MMA_F16(accs[nt], alo, bh);
                }
            }
        }

        float t0 = -1e30f, t1 = -1e30f;
        #pragma unroll
        for (int nt = 0; nt < 8; ++nt) {
            t0 = fmaxf(t0, fmaxf(accs[nt][0], accs[nt][1]));
            t1 = fmaxf(t1, fmaxf(accs[nt][2], accs[nt][3]));
        }
        t0 = fmaxf(t0, __shfl_xor_sync(0xffffffffu, t0, 1));
        t0 = fmaxf(t0, __shfl_xor_sync(0xffffffffu, t0, 2));
        t1 = fmaxf(t1, __shfl_xor_sync(0xffffffffu, t1, 1));
        t1 = fmaxf(t1, __shfl_xor_sync(0xffffffffu, t1, 2));
        float nm0 = fmaxf(m0, t0), nm1 = fmaxf(m1, t1);
        float sc0 = __expf(m0 - nm0), sc1 = __expf(m1 - nm1);

        uint32_t ph[4][4], pl[4][4];
        float ps0 = 0.f, ps1 = 0.f;
        #pragma unroll
        for (int kk = 0; kk < 4; ++kk) {
            float p00 = __expf(accs[2 * kk][0] - nm0);
            float p01 = __expf(accs[2 * kk][1] - nm0);
            float p02 = __expf(accs[2 * kk][2] - nm1);
            float p03 = __expf(accs[2 * kk][3] - nm1);
            float p10 = __expf(accs[2 * kk + 1][0] - nm0);
            float p11 = __expf(accs[2 * kk + 1][1] - nm0);
            float p12 = __expf(accs[2 * kk + 1][2] - nm1);
            float p13 = __expf(accs[2 * kk + 1][3] - nm1);
            ps0 += p00 + p01 + p10 + p11;
            ps1 += p02 + p03 + p12 + p13;
            split2h(p00, p01, ph[kk][0], pl[kk][0]);
            split2h(p02, p03, ph[kk][1], pl[kk][1]);
            split2h(p10, p11, ph[kk][2], pl[kk][2]);
            split2h(p12, p13, ph[kk][3], pl[kk][3]);
        }
        ps0 += __shfl_xor_sync(0xffffffffu, ps0, 1);
        ps0 += __shfl_xor_sync(0xffffffffu, ps0, 2);
        ps1 += __shfl_xor_sync(0xffffffffu, ps1, 1);
        ps1 += __shfl_xor_sync(0xffffffffu, ps1, 2);
        l0 = l0 * sc0 + ps0;
        l1 = l1 * sc1 + ps1;
        m0 = nm0;
        m1 = nm1;

        #pragma unroll
        for (int nt = 0; nt < 16; ++nt) {
            acco[nt][0] *= sc0; acco[nt][1] *= sc0;
            acco[nt][2] *= sc1; acco[nt][3] *= sc1;
        }

        #pragma unroll
        for (int ntp = 0; ntp < 8; ++ntp) {
            #pragma unroll
            for (int kk = 0; kk < 4; ++kk) {
                uint32_t v4[4];
                ldmB(v4, vb + (ntp * 16) * 72 + kk * 16, 72);
                #pragma unroll
                for (int half = 0; half < 2; ++half) {
                    uint32_t bv[2] = {v4[half * 2], v4[half * 2 + 1]};
                    int nt = ntp * 2 + half;
                    MMA_F16(acco[nt], ph[kk], bv);
                    MMA_F16(acco[nt], pl[kk], bv);
                }
            }
        }
        __syncthreads();
    }

    float i0 = 1.0f / l0, i1 = 1.0f / l1;
    int r0 = bm + arow;
    #pragma unroll
    for (int nt = 0; nt < 16; ++nt) {
        int col = nt * 8 + c * 2;
        if (col < HD_) {
            attno[(size_t)r0 * KP500 + h * HD_ + col]       = __float2half_rn(acco[nt][0] * i0);
            attno[(size_t)(r0 + 8) * KP500 + h * HD_ + col] = __float2half_rn(acco[nt][2] * i1);
        }
        if (col + 1 < HD_) {
            attno[(size_t)r0 * KP500 + h * HD_ + col + 1]       = __float2half_rn(acco[nt][1] * i0);
            attno[(size_t)(r0 + 8) * KP500 + h * HD_ + col + 1] = __float2half_rn(acco[nt][3] * i1);
        }
    }
}

// ---------------- fp16 GEMM with 3-stage cp.async pipeline -----------------------
// Chunk stream ci in [0, npairs*nchunk); one __syncthreads per chunk.
// modes as before. Dynamic smem: 9 * 5120 halfs = 92160 B.
#define GF_CH 5120                       // halfs per (array, stage)
#define GF_SMEM (9 * GF_CH * 2)

__global__ __launch_bounds__(512, 1)
void gemm_fh(const __half* __restrict__ A1, const __half* __restrict__ A2, int lda,
             const __half* __restrict__ B1h, const __half* __restrict__ B1l,
             const __half* __restrict__ B2h, const __half* __restrict__ B2l,
             int ldb,
             const float* __restrict__ bias,
             void* __restrict__ C_, int ldc,
             int Nfull, int Kpad, int relu, int mode, int ksplit,
             int npassB, float qscale) {
    extern __shared__ __half gsm[];
    __half* sA  = gsm;                   // [3][5120]
    __half* sBh = gsm + 3 * GF_CH;       // [3][5120]
    __half* sBl = gsm + 6 * GF_CH;       // [3][5120]

    const int tid  = threadIdx.x;
    const int lane = tid & 31;
    const int wid  = tid >> 5;
    const int wm   = wid & 3;
    const int wn   = wid >> 2;
    const int bm   = blockIdx.y * 128;
    const int bn   = blockIdx.x * 128;
    const int ks   = blockIdx.z % ksplit;
    const int klen = Kpad / ksplit;
    const int kb   = ks * klen;
    const int nchunk = klen / 32;
    const int npairs = (A2 != nullptr) ? 2 : 1;
    const int total  = npairs * nchunk;

    const int r  = tid >> 2;
    const int gq = tid & 3;
    const bool bok = (bn + r) < Nfull;

    // pre-zero out-of-range B rows in all stages (never cp.async'd)
    if (!bok) {
        #pragma unroll
        for (int s = 0; s < 3; ++s) {
            *(uint4*)(sBh + s * GF_CH + r * 40 + gq * 8) = make_uint4(0, 0, 0, 0);
            *(uint4*)(sBl + s * GF_CH + r * 40 + gq * 8) = make_uint4(0, 0, 0, 0);
        }
    }

    float acc[2][4][4];
    #pragma unroll
    for (int i = 0; i < 2; i++)
        #pragma unroll
        for (int j = 0; j < 4; j++)
            #pragma unroll
            for (int q = 0; q < 4; q++) acc[i][j][q] = 0.f;

    auto issue = [&](int ci, int st) {
        int pr = ci / nchunk;
        int k0 = kb + (ci - pr * nchunk) * 32;
        const __half* A  = pr ? A2 : A1;
        cpasync16(sA + st * GF_CH + r * 40 + gq * 8,
                  A + (size_t)(bm + r) * lda + k0 + gq * 8);
        if (bok) {
            const __half* Bh = pr ? B2h : B1h;
            cpasync16(sBh + st * GF_CH + r * 40 + gq * 8,
                      Bh + (size_t)(bn + r) * ldb + k0 + gq * 8);
            if (npassB > 1) {
                const __half* Bl = pr ? B2l : B1l;
                cpasync16(sBl + st * GF_CH + r * 40 + gq * 8,
                          Bl + (size_t)(bn + r) * ldb + k0 + gq * 8);
            }
        }
        CP_COMMIT();
    };

    issue(0, 0);
    issue(1, 1);

    for (int ci = 0; ci < total; ++ci) {
        if (ci + 1 < total) { CP_WAIT(1); } else { CP_WAIT(0); }
        __syncthreads();
        if (ci + 2 < total) issue(ci + 2, (ci + 2) % 3);

        const int st = ci % 3;
        const __half* cA  = sA  + st * GF_CH;
        const __half* cBh = sBh + st * GF_CH;
        const __half* cBl = sBl + st * GF_CH;

        #pragma unroll
        for (int ksf = 0; ksf < 2; ++ksf) {
            uint32_t a[2][4];
            #pragma unroll
            for (int mt = 0; mt < 2; ++mt)
                ldmA(a[mt], cA + (wm * 32 + mt * 16) * 40 + ksf * 16, 40);
            #pragma unroll
            for (int ntp = 0; ntp < 2; ++ntp) {
                uint32_t bh4[4], bl4[4];
                ldmB(bh4, cBh + (wn * 32 + ntp * 16) * 40 + ksf * 16, 40);
                if (npassB > 1)
                    ldmB(bl4, cBl + (wn * 32 + ntp * 16) * 40 + ksf * 16, 40);
                #pragma unroll
                for (int half = 0; half < 2; ++half) {
                    uint32_t bh[2] = {bh4[half * 2], bh4[half * 2 + 1]};
                    int nt = ntp * 2 + half;
                    #pragma unroll
                    for (int mt = 0; mt < 2; ++mt)
                        MMA_F16(acc[mt][nt], a[mt], bh);
                    if (npassB > 1) {
                        uint32_t bl[2] = {bl4[half * 2], bl4[half * 2 + 1]};
                        #pragma unroll
                        for (int mt = 0; mt < 2; ++mt)
                            MMA_F16(acc[mt][nt], a[mt], bl);
                    }
                }
            }
        }
    }

    if (mode == 0) {
        float* C = (float*)C_;
        #pragma unroll
        for (int mt = 0; mt < 2; ++mt) {
            int row = bm + wm * 32 + mt * 16 + (lane >> 2);
            #pragma unroll
            for (int nt = 0; nt < 4; ++nt) {
                int gc = bn + wn * 32 + nt * 8 + ((lane & 3) << 1);
                #pragma unroll
                for (int j = 0; j < 2; ++j) {
                    if (gc + j < Nfull) {
                        float bsv = bias ? bias[gc + j] : 0.f;
                        float v0 = acc[mt][nt][j] + bsv;
                        float v1 = acc[mt][nt][j + 2] + bsv;
                        if (relu) { v0 = fmaxf(v0, 0.f); v1 = fmaxf(v1, 0.f); }
                        C[(size_t)row * ldc + gc + j] = v0;
                        C[(size_t)(row + 8) * ldc + gc + j] = v1;
                    }
                }
            }
        }
    } else if (mode == 1) {
        float* C = (float*)C_;
        #pragma unroll
        for (int mt = 0; mt < 2; ++mt) {
            int row = bm + wm * 32 + mt * 16 + (lane >> 2);
            #pragma unroll
            for (int nt = 0; nt < 4; ++nt) {
                int gc = bn + wn * 32 + nt * 8 + ((lane & 3) << 1);
                #pragma unroll
                for (int j = 0; j < 2; ++j) {
                    if (gc + j < Nfull) {
                        atomicAdd(&C[(size_t)row * ldc + gc + j], acc[mt][nt][j]);
                        atomicAdd(&C[(size_t)(row + 8) * ldc + gc + j], acc[mt][nt][j + 2]);
                    }
                }
            }
        }
    } else if (mode == 2) {
        __half* C = (__half*)C_;
        #pragma unroll
        for (int mt = 0; mt < 2; ++mt) {
            int row = bm + wm * 32 + mt * 16 + (lane >> 2);
            #pragma unroll
            for (int nt = 0; nt < 4; ++nt) {
                int gc = bn + wn * 32 + nt * 8 + ((lane & 3) << 1);
                #pragma unroll
                for (int j = 0; j < 2; ++j) {
                    float v0 = 0.f, v1 = 0.f;
                    if (gc + j < Nfull) {
                        float bsv = bias ? bias[gc + j] : 0.f;
                        v0 = acc[mt][nt][j] + bsv;
                        v1 = acc[mt][nt][j + 2] + bsv;
                        if (relu) { v0 = fmaxf(v0, 0.f); v1 = fmaxf(v1, 0.f); }
                    }
                    C[(size_t)row * ldc + gc + j] = __float2half_rn(v0);
                    C[(size_t)(row + 8) * ldc + gc + j] = __float2half_rn(v1);
                }
            }
        }
    } else {
        // mode 3: qkv split epilogue
        #pragma unroll
        for (int mt = 0; mt < 2; ++mt) {
            int n0 = bm + wm * 32 + mt * 16 + (lane >> 2);
            int n1 = n0 + 8;
            #pragma unroll
            for (int nt = 0; nt < 4; ++nt) {
                int gc = bn + wn * 32 + nt * 8 + ((lane & 3) << 1);
                #pragma unroll
                for (int j = 0; j < 2; ++j) {
                    int cc = gc + j;
                    if (cc >= 3 * HH_) continue;
                    float v0 = acc[mt][nt][j]     + bias[cc];
                    float v1 = acc[mt][nt][j + 2] + bias[cc];
                    if (cc < HH_) {
                        int h = cc / HD_;
                        int d = cc - h * HD_;
                        size_t b0 = ((size_t)h * NN_ + n0) * HDP_ + d;
                        size_t b1 = ((size_t)h * NN_ + n1) * HDP_ + d;
                        __half hh, ll;
                        splitf_h(v0 * qscale, hh, ll);
                        g_qh[b0] = hh; g_ql[b0] = ll;
                        splitf_h(v1 * qscale, hh, ll);
                        g_qh[b1] = hh; g_ql[b1] = ll;
                    } else if (cc < 2 * HH_) {
                        int c2 = cc - HH_;
                        int h = c2 / HD_;
                        int d = c2 - h * HD_;
                        size_t b0 = ((size_t)h * NN_ + n0) * HDP_ + d;
                        size_t b1 = ((size_t)h * NN_ + n1) * HDP_ + d;
                        __half hh, ll;
                        splitf_h(v0, hh, ll);
                        g_kh[b0] = hh; g_kl[b0] = ll;
                        splitf_h(v1, hh, ll);
                        g_kh[b1] = hh; g_kl[b1] = ll;
                    } else {
                        int c2 = cc - 2 * HH_;
                        int h = c2 / HD_;
                        int d = c2 - h * HD_;
                        size_t base = ((size_t)h * HDP_ + d) * NN_;
                        g_vt[base + n0] = __float2half_rn(v0);
                        g_vt[base + n1] = __float2half_rn(v1);
                    }
                }
            }
        }
    }
}

// ---------------- launch -----------------------------------------------------
extern "C" void kernel_launch(void* const* d_in, const int* in_sizes, int n_in,
                              void* d_out, int out_size) {
    const float* x        = (const float*)d_in[0];
    const int*   ei       = (const int*)d_in[1];
    const float* W1_self  = (const float*)d_in[2];
    const float* W1_neigh = (const float*)d_in[3];
    const float* b1       = (const float*)d_in[4];
    const float* W_in     = (const float*)d_in[5];
    const float* b_in     = (const float*)d_in[6];
    const float* W_out    = (const float*)d_in[7];
    const float* b_out    = (const float*)d_in[8];
    const float* W2_self  = (const float*)d_in[9];
    const float* W2_neigh = (const float*)d_in[10];
    const float* b2       = (const float*)d_in[11];
    const float* Wc       = (const float*)d_in[12];
    const float* bc       = (const float*)d_in[13];

    float* out_x      = (float*)d_out;
    float* out_logits = (float*)d_out + (size_t)NN_ * OUT_;

    float* tmp2;
    __half *xh, *meanh, *h1h, *attnoh, *h2h, *outxh;
    cudaGetSymbolAddress((void**)&xh,     g_xh);
    cudaGetSymbolAddress((void**)&meanh,  g_meanh);
    cudaGetSymbolAddress((void**)&h1h,    g_h1h);
    cudaGetSymbolAddress((void**)&attnoh, g_attnoh);
    cudaGetSymbolAddress((void**)&h2h,    g_h2h);
    cudaGetSymbolAddress((void**)&tmp2,   g_tmp2);
    cudaGetSymbolAddress((void**)&outxh,  g_outxh);

    __half *qh, *ql, *kh, *kl, *vt;
    __half *w1sh, *w1sl, *w1nh, *w1nl, *winh, *winl, *woh, *wol;
    __half *w2sh, *w2sl, *w2nh, *w2nl, *wch, *wcl;
    cudaGetSymbolAddress((void**)&qh,   g_qh);
    cudaGetSymbolAddress((void**)&ql,   g_ql);
    cudaGetSymbolAddress((void**)&kh,   g_kh);
    cudaGetSymbolAddress((void**)&kl,   g_kl);
    cudaGetSymbolAddress((void**)&vt,   g_vt);
    cudaGetSymbolAddress((void**)&w1sh, g_w1sh); cudaGetSymbolAddress((void**)&w1sl, g_w1sl);
    cudaGetSymbolAddress((void**)&w1nh, g_w1nh); cudaGetSymbolAddress((void**)&w1nl, g_w1nl);
    cudaGetSymbolAddress((void**)&winh, g_winh); cudaGetSymbolAddress((void**)&winl, g_winl);
    cudaGetSymbolAddress((void**)&woh,  g_woh);  cudaGetSymbolAddress((void**)&wol,  g_wol);
    cudaGetSymbolAddress((void**)&w2sh, g_w2sh); cudaGetSymbolAddress((void**)&w2sl, g_w2sl);
    cudaGetSymbolAddress((void**)&w2nh, g_w2nh); cudaGetSymbolAddress((void**)&w2nl, g_w2nl);
    cudaGetSymbolAddress((void**)&wch,  g_wch);  cudaGetSymbolAddress((void**)&wcl,  g_wcl);

    cudaFuncSetAttribute(flash_attn, cudaFuncAttributeMaxDynamicSharedMemorySize, FLASH_SMEM);
    cudaFuncSetAttribute(gemm_fh, cudaFuncAttributeMaxDynamicSharedMemorySize, GF_SMEM);

    const float scale = 1.0f / sqrtf((float)HD_);

    // 1. fused prep (weight splits + x convert + tmp2 zero)
    prep_all<<<(unsigned)((SW_TOTAL + 255) / 256), 256>>>(W1_self, W1_neigh, W_in,
                                                          W_out, W2_self, W2_neigh, Wc, x);
    // 2-4. CSR build (g_degi is zero at entry; scan resets it)
    count_deg<<<EE_ / 256, 256>>>(ei);
    scan_offsets<<<1, 1024>>>();
    csr_fill<<<EE_ / 256, 256>>>(ei);
    // 5. gather mean of x
    gather_mean_h<<<NN_, 64>>>(xh, meanh);
    // 6. SAGE1 (fp16 out)
    {
        dim3 grid(4, 32, 1);
        gemm_fh<<<grid, 512, GF_SMEM>>>(xh, meanh, KP500, w1sh, w1sl, w1nh, w1nl, KP500,
                                        b1, h1h, KP500, HH_, KP500, 1, 2, 1, 2, 0.f);
    }
    // 7. qkv projection with fused q/k/v split epilogue
    {
        dim3 grid(12, 32, 1);
        gemm_fh<<<grid, 512, GF_SMEM>>>(h1h, nullptr, KP500, winh, winl, nullptr, nullptr, KP500,
                                        b_in, nullptr, 0, 3 * HH_, KP500, 0, 3, 1, 2, scale);
    }
    // 8. flash attention
    {
        dim3 grid(NN_ / 128, NHEAD);
        flash_attn<<<grid, 256, FLASH_SMEM>>>(qh, ql, kh, kl, vt, attnoh);
    }
    // 9. out projection (fp16 out)
    {
        dim3 grid(4, 32, 1);
        gemm_fh<<<grid, 512, GF_SMEM>>>(attnoh, nullptr, KP500, woh, wol, nullptr, nullptr, KP500,
                                        b_out, h2h, KP500, HH_, KP500, 1, 2, 1, 2, 0.f);
    }
    // 10. gather mean of h2
    gather_mean_h<<<NN_, 64>>>(h2h, meanh);
    // 11. SAGE2 (split-K=4 atomic; tmp2 pre-zeroed in prep)
    {
        dim3 grid(1, 32, 4);
        gemm_fh<<<grid, 512, GF_SMEM>>>(h2h, meanh, KP500, w2sh, w2sl, w2nh, w2nl, KP500,
                                        nullptr, tmp2, OUT_, OUT_, KP500, 0, 1, 4, 2, 0.f);
    }
    // 12. bias+relu dual write
    bias_relu2<<<(NN_ * 128 + 255) / 256, 256>>>(tmp2, b2, out_x);
    // 13. classifier (single-pass fp16)
    {
        dim3 grid(CCP_ / 128, 32, 1);
        gemm_fh<<<grid, 512, GF_SMEM>>>(outxh, nullptr, 128, wch, wcl, nullptr, nullptr, 128,
                                        bc, out_logits, CC_, CC_, 128, 0, 0, 1, 1, 0.f);
    }
}

// round 16
// speedup vs baseline: 1.0583x; 1.0400x over previous
#include <cuda_runtime.h>
#include <cuda_fp16.h>
#include <math.h>
#include <stdint.h>

#define NN_   4096
#define EE_   131072
#define IN_   500
#define HH_   500
#define OUT_  100
#define CC_   15451
#define CCP_  15488
#define NHEAD 4
#define HD_   125
#define HDP_  128
#define KP500 512
#define NKT   (NN_ / 64)

// ---------------- scratch ----------------------------------------------------
__device__ int    g_degi[NN_];     // zero at every call entry (scan resets it)
__device__ int    g_off[NN_ + 1];
__device__ int    g_cur[NN_];
__device__ int    g_csr[EE_];
__device__ __half g_xh[NN_ * KP500];
__device__ __half g_meanh[NN_ * KP500];
__device__ __half g_h1h[NN_ * KP500];
__device__ __half g_attnoh[NN_ * KP500];   // pads stay zero forever
__device__ __half g_h2h[NN_ * KP500];
__device__ float  g_tmp2[NN_ * OUT_];
__device__ __half g_outxh[NN_ * 128];

__device__ __half g_qh[NHEAD * NN_ * HDP_];   // pads d=125..127 stay zero forever
__device__ __half g_kh[NHEAD * NN_ * HDP_];
__device__ __half g_kl[NHEAD * NN_ * HDP_];
__device__ __half g_vt[NHEAD * HDP_ * NN_];

__device__ __half g_w1sh[HH_ * KP500], g_w1sl[HH_ * KP500];
__device__ __half g_w1nh[HH_ * KP500], g_w1nl[HH_ * KP500];
__device__ __half g_winh[3 * HH_ * KP500], g_winl[3 * HH_ * KP500];
__device__ __half g_woh[HH_ * KP500], g_wol[HH_ * KP500];
__device__ __half g_w2sh[OUT_ * KP500], g_w2sl[OUT_ * KP500];
__device__ __half g_w2nh[OUT_ * KP500], g_w2nl[OUT_ * KP500];
__device__ __half g_wch[(size_t)CC_ * 128], g_wcl[(size_t)CC_ * 128];

// ---------------- helpers ----------------------------------------------------
__device__ __forceinline__ void splitf_h(float x, __half& h, __half& l) {
    h = __float2half_rn(x);
    l = __float2half_rn(x - __half2float(h));
}
__device__ __forceinline__ void split2h(float x, float y, uint32_t& hi, uint32_t& lo) {
    __half hx = __float2half_rn(x), hy = __float2half_rn(y);
    __half lx = __float2half_rn(x - __half2float(hx));
    __half ly = __float2half_rn(y - __half2float(hy));
    __half2 h2; h2.x = hx; h2.y = hy;
    __half2 l2; l2.x = lx; l2.y = ly;
    hi = *(uint32_t*)&h2;
    lo = *(uint32_t*)&l2;
}
__device__ __forceinline__ void cpasync16(void* sp, const void* gp) {
    uint32_t s = (uint32_t)__cvta_generic_to_shared(sp);
    asm volatile("cp.async.cg.shared.global [%0], [%1], 16;" :: "r"(s), "l"(gp));
}
#define CP_COMMIT() asm volatile("cp.async.commit_group;")
#define CP_WAIT(n)  asm volatile("cp.async.wait_group %0;" :: "n"(n))

#define MMA_F16(d, a, b) \
  asm volatile("mma.sync.aligned.m16n8k16.row.col.f32.f16.f16.f32 " \
   "{%0,%1,%2,%3},{%4,%5,%6,%7},{%8,%9},{%0,%1,%2,%3};" \
   : "+f"((d)[0]), "+f"((d)[1]), "+f"((d)[2]), "+f"((d)[3]) \
   : "r"((a)[0]), "r"((a)[1]), "r"((a)[2]), "r"((a)[3]), "r"((b)[0]), "r"((b)[1]))

__device__ __forceinline__ void ldmA(uint32_t* r, const __half* base, int S) {
    int l = threadIdx.x & 31;
    const __half* p = (l < 16) ? (base + l * S) : (base + (l - 16) * S + 8);
    uint32_t a = (uint32_t)__cvta_generic_to_shared(p);
    asm volatile("ldmatrix.sync.aligned.m8n8.x4.shared.b16 {%0,%1,%2,%3}, [%4];"
                 : "=r"(r[0]), "=r"(r[1]), "=r"(r[2]), "=r"(r[3]) : "r"(a));
}
__device__ __forceinline__ void ldmB(uint32_t* r, const __half* base, int S) {
    int l = threadIdx.x & 31;
    int q = l >> 3, rr = l & 7;
    const __half* p = base + (rr + ((q >> 1) << 3)) * S + ((q & 1) << 3);
    uint32_t a = (uint32_t)__cvta_generic_to_shared(p);
    asm volatile("ldmatrix.sync.aligned.m8n8.x4.shared.b16 {%0,%1,%2,%3}, [%4];"
                 : "=r"(r[0]), "=r"(r[1]), "=r"(r[2]), "=r"(r[3]) : "r"(a));
}

// ---------------- CSR --------------------------------------------------------
__global__ void count_deg(const int* __restrict__ ei) {
    int e = blockIdx.x * blockDim.x + threadIdx.x;
    if (e < EE_) atomicAdd(&g_degi[ei[EE_ + e]], 1);
}
__global__ __launch_bounds__(1024) void scan_offsets() {
    __shared__ int s[1024];
    int t = threadIdx.x;
    int base = t * 4;
    int lp[4];
    int sum = 0;
    #pragma unroll
    for (int i = 0; i < 4; i++) {
        int v = g_degi[base + i];
        g_degi[base + i] = 0;
        lp[i] = sum; sum += v;
    }
    s[t] = sum;
    __syncthreads();
    for (int off = 1; off < 1024; off <<= 1) {
        int x = (t >= off) ? s[t - off] : 0;
        __syncthreads();
        s[t] += x;
        __syncthreads();
    }
    int excl = (t > 0) ? s[t - 1] : 0;
    #pragma unroll
    for (int i = 0; i < 4; i++) {
        int o = excl + lp[i];
        g_off[base + i] = o;
        g_cur[base + i] = o;
    }
    if (t == 1023) g_off[NN_] = s[1023];
}
__global__ void csr_fill(const int* __restrict__ ei) {
    int e = blockIdx.x * blockDim.x + threadIdx.x;
    if (e >= EE_) return;
    int d = ei[EE_ + e];
    int pos = atomicAdd(&g_cur[d], 1);
    g_csr[pos] = ei[e];
}

// ---------------- fp16 gather-mean ---------------------------------------------
__global__ __launch_bounds__(64) void gather_mean_h(const __half* __restrict__ feat,
                                                    __half* __restrict__ mean) {
    int node = blockIdx.x;
    int t = threadIdx.x;
    int beg = g_off[node], end = g_off[node + 1];
    float acc[8];
    #pragma unroll
    for (int i = 0; i < 8; i++) acc[i] = 0.f;
    for (int e = beg; e < end; ++e) {
        int s0 = __ldg(&g_csr[e]);
        uint4 v = *(const uint4*)(feat + (size_t)s0 * KP500 + t * 8);
        const __half2* h2 = (const __half2*)&v;
        #pragma unroll
        for (int i = 0; i < 4; i++) {
            float2 f = __half22float2(h2[i]);
            acc[2 * i]     += f.x;
            acc[2 * i + 1] += f.y;
        }
    }
    float inv = 1.0f / fmaxf((float)(end - beg), 1.0f);
    uint4 o;
    __half2* oh = (__half2*)&o;
    #pragma unroll
    for (int i = 0; i < 4; i++)
        oh[i] = __floats2half2_rn(acc[2 * i] * inv, acc[2 * i + 1] * inv);
    *(uint4*)(mean + (size_t)node * KP500 + t * 8) = o;
}

// ---------------- fused prep -----------------------------------------------------
__device__ __forceinline__ void split_elem(const float* __restrict__ W,
                                           __half* __restrict__ hi,
                                           __half* __restrict__ lo,
                                           int Kr, int Kpad, long long local) {
    int k = (int)(local % Kpad);
    long long n = local / Kpad;
    float v = (k < Kr) ? W[n * Kr + k] : 0.f;
    splitf_h(v, hi[local], lo[local]);
}
#define SW_S0 (HH_ * KP500)
#define SW_S1 (2 * HH_ * KP500)
#define SW_S2 (SW_S1 + 3 * HH_ * KP500)
#define SW_S3 (SW_S2 + HH_ * KP500)
#define SW_S4 (SW_S3 + OUT_ * KP500)
#define SW_S5 (SW_S4 + OUT_ * KP500)
#define SW_S6 (SW_S5 + (long long)CC_ * 128)
#define SW_S7 (SW_S6 + NN_ * KP500)
#define SW_TOTAL (SW_S7 + NN_ * OUT_)

__global__ void prep_all(const float* __restrict__ W1s, const float* __restrict__ W1n,
                         const float* __restrict__ Win, const float* __restrict__ Wo,
                         const float* __restrict__ W2s, const float* __restrict__ W2n,
                         const float* __restrict__ Wc, const float* __restrict__ x) {
    long long idx = (long long)blockIdx.x * 256 + threadIdx.x;
    if (idx < SW_S0)      split_elem(W1s, g_w1sh, g_w1sl, IN_, KP500, idx);
    else if (idx < SW_S1) split_elem(W1n, g_w1nh, g_w1nl, IN_, KP500, idx - SW_S0);
    else if (idx < SW_S2) split_elem(Win, g_winh, g_winl, HH_, KP500, idx - SW_S1);
    else if (idx < SW_S3) split_elem(Wo,  g_woh,  g_wol,  HH_, KP500, idx - SW_S2);
    else if (idx < SW_S4) split_elem(W2s, g_w2sh, g_w2sl, HH_, KP500, idx - SW_S3);
    else if (idx < SW_S5) split_elem(W2n, g_w2nh, g_w2nl, HH_, KP500, idx - SW_S4);
    else if (idx < SW_S6) split_elem(Wc,  g_wch,  g_wcl,  OUT_, 128, idx - SW_S5);
    else if (idx < SW_S7) {
        long long j = idx - SW_S6;
        int col = (int)(j & (KP500 - 1));
        int n   = (int)(j >> 9);
        float v = (col < IN_) ? x[(size_t)n * IN_ + col] : 0.f;
        g_xh[j] = __float2half_rn(v);
    } else if (idx < SW_TOTAL) {
        g_tmp2[idx - SW_S7] = 0.f;
    }
}

__global__ void bias_relu2(const float* __restrict__ in, const float* __restrict__ b,
                           float* __restrict__ outf) {
    int idx = blockIdx.x * 256 + threadIdx.x;
    if (idx >= NN_ * 128) return;
    int col = idx & 127;
    int n   = idx >> 7;
    float v = 0.f;
    if (col < OUT_) {
        v = fmaxf(in[(size_t)n * OUT_ + col] + b[col], 0.f);
        outf[(size_t)n * OUT_ + col] = v;
    }
    g_outxh[idx] = __float2half_rn(v);
}

// ---------------- flash attention (QK 2-pass: Q-hi x K hi/lo; PV 2-pass) -------
#define FQS (128 * 136)
#define FKS (64 * 136)
#define FVS (128 * 72)
#define FLASH_SMEM ((FQS + 4 * FKS + 2 * FVS) * 2)

__global__ __launch_bounds__(256)
void flash_attn(const __half* __restrict__ qh,
                const __half* __restrict__ kh, const __half* __restrict__ kl,
                const __half* __restrict__ vt,
                __half* __restrict__ attno) {
    extern __shared__ __half sm[];
    __half* sQh = sm;
    __half* sKb = sm + FQS;
    __half* sVb = sm + FQS + 4 * FKS;

    const int tid  = threadIdx.x;
    const int lane = tid & 31;
    const int wid  = tid >> 5;
    const int g    = lane >> 2;
    const int c    = lane & 3;
    const int bm   = blockIdx.x * 128;
    const int h    = blockIdx.y;

    const __half* qhp = qh + ((size_t)h * NN_ + bm) * HDP_;
    const __half* khp = kh + (size_t)h * NN_ * HDP_;
    const __half* klp = kl + (size_t)h * NN_ * HDP_;
    const __half* vp  = vt + (size_t)h * HDP_ * NN_;

    #pragma unroll
    for (int i = 0; i < 8; i++) {
        int idx = tid + i * 256;
        int row = idx >> 4;
        int ch  = idx & 15;
        cpasync16(sQh + row * 136 + ch * 8, qhp + (size_t)row * HDP_ + ch * 8);
    }

    auto kvload = [&](int j, int buf) {
        __half* kb = sKb + buf * 2 * FKS;
        __half* vb = sVb + buf * FVS;
        const int key0 = j * 64;
        #pragma unroll
        for (int i = 0; i < 8; i++) {
            int idx = tid + i * 256;
            int hf  = idx >> 10;
            int rem = idx & 1023;
            int row = rem >> 4;
            int ch  = rem & 15;
            const __half* src = (hf ? klp : khp) + (size_t)(key0 + row) * HDP_ + ch * 8;
            cpasync16(kb + hf * FKS + row * 136 + ch * 8, src);
        }
        #pragma unroll
        for (int i = 0; i < 4; i++) {
            int idx = tid + i * 256;
            int row = idx >> 3;
            int ch  = idx & 7;
            const __half* src = vp + (size_t)row * NN_ + key0 + ch * 8;
            cpasync16(vb + row * 72 + ch * 8, src);
        }
    };

    kvload(0, 0);
    CP_COMMIT();

    float m0 = -1e30f, m1 = -1e30f, l0 = 0.f, l1 = 0.f;
    float acco[16][4];
    #pragma unroll
    for (int i = 0; i < 16; i++)
        #pragma unroll
        for (int q = 0; q < 4; q++) acco[i][q] = 0.f;

    const int arow = wid * 16 + g;

    for (int j = 0; j < NKT; ++j) {
        if (j + 1 < NKT) {
            kvload(j + 1, (j + 1) & 1);
            CP_COMMIT();
            CP_WAIT(1);
        } else {
            CP_WAIT(0);
        }
        __syncthreads();

        const __half* kbh = sKb + (j & 1) * 2 * FKS;
        const __half* kbl = kbh + FKS;
        const __half* vb  = sVb + (j & 1) * FVS;

        float accs[8][4];
        #pragma unroll
        for (int i = 0; i < 8; i++)
            #pragma unroll
            for (int q = 0; q < 4; q++) accs[i][q] = 0.f;

        // ---- S = Q @ K^T (2-pass: Q-hi x K hi/lo) ----
        #pragma unroll
        for (int ks = 0; ks < 8; ++ks) {
            uint32_t ahh[4];
            ldmA(ahh, sQh + (wid * 16) * 136 + ks * 16, 136);
            #pragma unroll
            for (int ntp = 0; ntp < 4; ++ntp) {
                uint32_t bh4[4], bl4[4];
                ldmB(bh4, kbh + (ntp * 16) * 136 + ks * 16, 136);
                ldmB(bl4, kbl + (ntp * 16) * 136 + ks * 16, 136);
                #pragma unroll
                for (int half = 0; half < 2; ++half) {
                    uint32_t bh[2] = {bh4[half * 2], bh4[half * 2 + 1]};
                    uint32_t bl[2] = {bl4[half * 2], bl4[half * 2 + 1]};
                    int nt = ntp * 2 + half;
                    MMA_F16(accs[nt], ahh, bh);
                    MMA_F16(accs[nt], ahh, bl);
                }
            }
        }

        float t0 = -1e30f, t1 = -1e30f;
        #pragma unroll
        for (int nt = 0; nt < 8; ++nt) {
            t0 = fmaxf(t0, fmaxf(accs[nt][0], accs[nt][1]));
            t1 = fmaxf(t1, fmaxf(accs[nt][2], accs[nt][3]));
        }
        t0 = fmaxf(t0, __shfl_xor_sync(0xffffffffu, t0, 1));
        t0 = fmaxf(t0, __shfl_xor_sync(0xffffffffu, t0, 2));
        t1 = fmaxf(t1, __shfl_xor_sync(0xffffffffu, t1, 1));
        t1 = fmaxf(t1, __shfl_xor_sync(0xffffffffu, t1, 2));
        float nm0 = fmaxf(m0, t0), nm1 = fmaxf(m1, t1);
        float sc0 = __expf(m0 - nm0), sc1 = __expf(m1 - nm1);

        uint32_t ph[4][4], pl[4][4];
        float ps0 = 0.f, ps1 = 0.f;
        #pragma unroll
        for (int kk = 0; kk < 4; ++kk) {
            float p00 = __expf(accs[2 * kk][0] - nm0);
            float p01 = __expf(accs[2 * kk][1] - nm0);
            float p02 = __expf(accs[2 * kk][2] - nm1);
            float p03 = __expf(accs[2 * kk][3] - nm1);
            float p10 = __expf(accs[2 * kk + 1][0] - nm0);
            float p11 = __expf(accs[2 * kk + 1][1] - nm0);
            float p12 = __expf(accs[2 * kk + 1][2] - nm1);
            float p13 = __expf(accs[2 * kk + 1][3] - nm1);
            ps0 += p00 + p01 + p10 + p11;
            ps1 += p02 + p03 + p12 + p13;
            split2h(p00, p01, ph[kk][0], pl[kk][0]);
            split2h(p02, p03, ph[kk][1], pl[kk][1]);
            split2h(p10, p11, ph[kk][2], pl[kk][2]);
            split2h(p12, p13, ph[kk][3], pl[kk][3]);
        }
        ps0 += __shfl_xor_sync(0xffffffffu, ps0, 1);
        ps0 += __shfl_xor_sync(0xffffffffu, ps0, 2);
        ps1 += __shfl_xor_sync(0xffffffffu, ps1, 1);
        ps1 += __shfl_xor_sync(0xffffffffu, ps1, 2);
        l0 = l0 * sc0 + ps0;
        l1 = l1 * sc1 + ps1;
        m0 = nm0;
        m1 = nm1;

        #pragma unroll
        for (int nt = 0; nt < 16; ++nt) {
            acco[nt][0] *= sc0; acco[nt][1] *= sc0;
            acco[nt][2] *= sc1; acco[nt][3] *= sc1;
        }

        #pragma unroll
        for (int ntp = 0; ntp < 8; ++ntp) {
            #pragma unroll
            for (int kk = 0; kk < 4; ++kk) {
                uint32_t v4[4];
                ldmB(v4, vb + (ntp * 16) * 72 + kk * 16, 72);
                #pragma unroll
                for (int half = 0; half < 2; ++half) {
                    uint32_t bv[2] = {v4[half * 2], v4[half * 2 + 1]};
                    int nt = ntp * 2 + half;
                    MMA_F16(acco[nt], ph[kk], bv);
                    MMA_F16(acco[nt], pl[kk], bv);
                }
            }
        }
        __syncthreads();
    }

    float i0 = 1.0f / l0, i1 = 1.0f / l1;
    int r0 = bm + arow;
    #pragma unroll
    for (int nt = 0; nt < 16; ++nt) {
        int col = nt * 8 + c * 2;
        if (col < HD_) {
            attno[(size_t)r0 * KP500 + h * HD_ + col]       = __float2half_rn(acco[nt][0] * i0);
            attno[(size_t)(r0 + 8) * KP500 + h * HD_ + col] = __float2half_rn(acco[nt][2] * i1);
        }
        if (col + 1 < HD_) {
            attno[(size_t)r0 * KP500 + h * HD_ + col + 1]       = __float2half_rn(acco[nt][1] * i0);
            attno[(size_t)(r0 + 8) * KP500 + h * HD_ + col + 1] = __float2half_rn(acco[nt][3] * i1);
        }
    }
}

// ---------------- fp16 GEMM with 3-stage cp.async pipeline -----------------------
#define GF_CH 5120
#define GF_SMEM (9 * GF_CH * 2)

__global__ __launch_bounds__(512, 1)
void gemm_fh(const __half* __restrict__ A1, const __half* __restrict__ A2, int lda,
             const __half* __restrict__ B1h, const __half* __restrict__ B1l,
             const __half* __restrict__ B2h, const __half* __restrict__ B2l,
             int ldb,
             const float* __restrict__ bias,
             void* __restrict__ C_, int ldc,
             int Nfull, int Kpad, int relu, int mode, int ksplit,
             int npassB, float qscale) {
    extern __shared__ __half gsm[];
    __half* sA  = gsm;
    __half* sBh = gsm + 3 * GF_CH;
    __half* sBl = gsm + 6 * GF_CH;

    const int tid  = threadIdx.x;
    const int lane = tid & 31;
    const int wid  = tid >> 5;
    const int wm   = wid & 3;
    const int wn   = wid >> 2;
    const int bm   = blockIdx.y * 128;
    const int bn   = blockIdx.x * 128;
    const int ks   = blockIdx.z % ksplit;
    const int klen = Kpad / ksplit;
    const int kb   = ks * klen;
    const int nchunk = klen / 32;
    const int npairs = (A2 != nullptr) ? 2 : 1;
    const int total  = npairs * nchunk;

    const int r  = tid >> 2;
    const int gq = tid & 3;
    const bool bok = (bn + r) < Nfull;

    if (!bok) {
        #pragma unroll
        for (int s = 0; s < 3; ++s) {
            *(uint4*)(sBh + s * GF_CH + r * 40 + gq * 8) = make_uint4(0, 0, 0, 0);
            *(uint4*)(sBl + s * GF_CH + r * 40 + gq * 8) = make_uint4(0, 0, 0, 0);
        }
    }

    float acc[2][4][4];
    #pragma unroll
    for (int i = 0; i < 2; i++)
        #pragma unroll
        for (int j = 0; j < 4; j++)
            #pragma unroll
            for (int q = 0; q < 4; q++) acc[i][j][q] = 0.f;

    auto issue = [&](int ci, int st) {
        int pr = ci / nchunk;
        int k0 = kb + (ci - pr * nchunk) * 32;
        const __half* A  = pr ? A2 : A1;
        cpasync16(sA + st * GF_CH + r * 40 + gq * 8,
                  A + (size_t)(bm + r) * lda + k0 + gq * 8);
        if (bok) {
            const __half* Bh = pr ? B2h : B1h;
            cpasync16(sBh + st * GF_CH + r * 40 + gq * 8,
                      Bh + (size_t)(bn + r) * ldb + k0 + gq * 8);
            if (npassB > 1) {
                const __half* Bl = pr ? B2l : B1l;
                cpasync16(sBl + st * GF_CH + r * 40 + gq * 8,
                          Bl + (size_t)(bn + r) * ldb + k0 + gq * 8);
            }
        }
        CP_COMMIT();
    };

    issue(0, 0);
    issue(1, 1);

    for (int ci = 0; ci < total; ++ci) {
        if (ci + 1 < total) { CP_WAIT(1); } else { CP_WAIT(0); }
        __syncthreads();
        if (ci + 2 < total) issue(ci + 2, (ci + 2) % 3);

        const int st = ci % 3;
        const __half* cA  = sA  + st * GF_CH;
        const __half* cBh = sBh + st * GF_CH;
        const __half* cBl = sBl + st * GF_CH;

        #pragma unroll
        for (int ksf = 0; ksf < 2; ++ksf) {
            uint32_t a[2][4];
            #pragma unroll
            for (int mt = 0; mt < 2; ++mt)
                ldmA(a[mt], cA + (wm * 32 + mt * 16) * 40 + ksf * 16, 40);
            #pragma unroll
            for (int ntp = 0; ntp < 2; ++ntp) {
                uint32_t bh4[4], bl4[4];
                ldmB(bh4, cBh + (wn * 32 + ntp * 16) * 40 + ksf * 16, 40);
                if (npassB > 1)
                    ldmB(bl4, cBl + (wn * 32 + ntp * 16) * 40 + ksf * 16, 40);
                #pragma unroll
                for (int half = 0; half < 2; ++half) {
                    uint32_t bh[2] = {bh4[half * 2], bh4[half * 2 + 1]};
                    int nt = ntp * 2 + half;
                    #pragma unroll
                    for (int mt = 0; mt < 2; ++mt)
                        MMA_F16(acc[mt][nt], a[mt], bh);
                    if (npassB > 1) {
                        uint32_t bl[2] = {bl4[half * 2], bl4[half * 2 + 1]};
                        #pragma unroll
                        for (int mt = 0; mt < 2; ++mt)
                            MMA_F16(acc[mt][nt], a[mt], bl);
                    }
                }
            }
        }
    }

    if (mode == 0) {
        float* C = (float*)C_;
        #pragma unroll
        for (int mt = 0; mt < 2; ++mt) {
            int row = bm + wm * 32 + mt * 16 + (lane >> 2);
            #pragma unroll
            for (int nt = 0; nt < 4; ++nt) {
                int gc = bn + wn * 32 + nt * 8 + ((lane & 3) << 1);
                #pragma unroll
                for (int j = 0; j < 2; ++j) {
                    if (gc + j < Nfull) {
                        float bsv = bias ? bias[gc + j] : 0.f;
                        float v0 = acc[mt][nt][j] + bsv;
                        float v1 = acc[mt][nt][j + 2] + bsv;
                        if (relu) { v0 = fmaxf(v0, 0.f); v1 = fmaxf(v1, 0.f); }
                        C[(size_t)row * ldc + gc + j] = v0;
                        C[(size_t)(row + 8) * ldc + gc + j] = v1;
                    }
                }
            }
        }
    } else if (mode == 1) {
        float* C = (float*)C_;
        #pragma unroll
        for (int mt = 0; mt < 2; ++mt) {
            int row = bm + wm * 32 + mt * 16 + (lane >> 2);
            #pragma unroll
            for (int nt = 0; nt < 4; ++nt) {
                int gc = bn + wn * 32 + nt * 8 + ((lane & 3) << 1);
                #pragma unroll
                for (int j = 0; j < 2; ++j) {
                    if (gc + j < Nfull) {
                        atomicAdd(&C[(size_t)row * ldc + gc + j], acc[mt][nt][j]);
                        atomicAdd(&C[(size_t)(row + 8) * ldc + gc + j], acc[mt][nt][j + 2]);
                    }
                }
            }
        }
    } else if (mode == 2) {
        __half* C = (__half*)C_;
        #pragma unroll
        for (int mt = 0; mt < 2; ++mt) {
            int row = bm + wm * 32 + mt * 16 + (lane >> 2);
            #pragma unroll
            for (int nt = 0; nt < 4; ++nt) {
                int gc = bn + wn * 32 + nt * 8 + ((lane & 3) << 1);
                #pragma unroll
                for (int j = 0; j < 2; ++j) {
                    float v0 = 0.f, v1 = 0.f;
                    if (gc + j < Nfull) {
                        float bsv = bias ? bias[gc + j] : 0.f;
                        v0 = acc[mt][nt][j] + bsv;
                        v1 = acc[mt][nt][j + 2] + bsv;
                        if (relu) { v0 = fmaxf(v0, 0.f); v1 = fmaxf(v1, 0.f); }
                    }
                    C[(size_t)row * ldc + gc + j] = __float2half_rn(v0);
                    C[(size_t)(row + 8) * ldc + gc + j] = __float2half_rn(v1);
                }
            }
        }
    } else {
        // mode 3: qkv split epilogue (q: hi only, scaled; k: hi/lo; v: transposed)
        #pragma unroll
        for (int mt = 0; mt < 2; ++mt) {
            int n0 = bm + wm * 32 + mt * 16 + (lane >> 2);
            int n1 = n0 + 8;
            #pragma unroll
            for (int nt = 0; nt < 4; ++nt) {
                int gc = bn + wn * 32 + nt * 8 + ((lane & 3) << 1);
                #pragma unroll
                for (int j = 0; j < 2; ++j) {
                    int cc = gc + j;
                    if (cc >= 3 * HH_) continue;
                    float v0 = acc[mt][nt][j]     + bias[cc];
                    float v1 = acc[mt][nt][j + 2] + bias[cc];
                    if (cc < HH_) {
                        int h = cc / HD_;
                        int d = cc - h * HD_;
                        size_t b0 = ((size_t)h * NN_ + n0) * HDP_ + d;
                        size_t b1 = ((size_t)h * NN_ + n1) * HDP_ + d;
                        g_qh[b0] = __float2half_rn(v0 * qscale);
                        g_qh[b1] = __float2half_rn(v1 * qscale);
                    } else if (cc < 2 * HH_) {
                        int c2 = cc - HH_;
                        int h = c2 / HD_;
                        int d = c2 - h * HD_;
                        size_t b0 = ((size_t)h * NN_ + n0) * HDP_ + d;
                        size_t b1 = ((size_t)h * NN_ + n1) * HDP_ + d;
                        __half hh, ll;
                        splitf_h(v0, hh, ll);
                        g_kh[b0] = hh; g_kl[b0] = ll;
                        splitf_h(v1, hh, ll);
                        g_kh[b1] = hh; g_kl[b1] = ll;
                    } else {
                        int c2 = cc - 2 * HH_;
                        int h = c2 / HD_;
                        int d = c2 - h * HD_;
                        size_t base = ((size_t)h * HDP_ + d) * NN_;
                        g_vt[base + n0] = __float2half_rn(v0);
                        g_vt[base + n1] = __float2half_rn(v1);
                    }
                }
            }
        }
    }
}

// ---------------- launch -----------------------------------------------------
extern "C" void kernel_launch(void* const* d_in, const int* in_sizes, int n_in,
                              void* d_out, int out_size) {
    const float* x        = (const float*)d_in[0];
    const int*   ei       = (const int*)d_in[1];
    const float* W1_self  = (const float*)d_in[2];
    const float* W1_neigh = (const float*)d_in[3];
    const float* b1       = (const float*)d_in[4];
    const float* W_in     = (const float*)d_in[5];
    const float* b_in     = (const float*)d_in[6];
    const float* W_out    = (const float*)d_in[7];
    const float* b_out    = (const float*)d_in[8];
    const float* W2_self  = (const float*)d_in[9];
    const float* W2_neigh = (const float*)d_in[10];
    const float* b2       = (const float*)d_in[11];
    const float* Wc       = (const float*)d_in[12];
    const float* bc       = (const float*)d_in[13];

    float* out_x      = (float*)d_out;
    float* out_logits = (float*)d_out + (size_t)NN_ * OUT_;

    float* tmp2;
    __half *xh, *meanh, *h1h, *attnoh, *h2h, *outxh;
    cudaGetSymbolAddress((void**)&xh,     g_xh);
    cudaGetSymbolAddress((void**)&meanh,  g_meanh);
    cudaGetSymbolAddress((void**)&h1h,    g_h1h);
    cudaGetSymbolAddress((void**)&attnoh, g_attnoh);
    cudaGetSymbolAddress((void**)&h2h,    g_h2h);
    cudaGetSymbolAddress((void**)&tmp2,   g_tmp2);
    cudaGetSymbolAddress((void**)&outxh,  g_outxh);

    __half *qh, *kh, *kl, *vt;
    __half *w1sh, *w1sl, *w1nh, *w1nl, *winh, *winl, *woh, *wol;
    __half *w2sh, *w2sl, *w2nh, *w2nl, *wch, *wcl;
    cudaGetSymbolAddress((void**)&qh,   g_qh);
    cudaGetSymbolAddress((void**)&kh,   g_kh);
    cudaGetSymbolAddress((void**)&kl,   g_kl);
    cudaGetSymbolAddress((void**)&vt,   g_vt);
    cudaGetSymbolAddress((void**)&w1sh, g_w1sh); cudaGetSymbolAddress((void**)&w1sl, g_w1sl);
    cudaGetSymbolAddress((void**)&w1nh, g_w1nh); cudaGetSymbolAddress((void**)&w1nl, g_w1nl);
    cudaGetSymbolAddress((void**)&winh, g_winh); cudaGetSymbolAddress((void**)&winl, g_winl);
    cudaGetSymbolAddress((void**)&woh,  g_woh);  cudaGetSymbolAddress((void**)&wol,  g_wol);
    cudaGetSymbolAddress((void**)&w2sh, g_w2sh); cudaGetSymbolAddress((void**)&w2sl, g_w2sl);
    cudaGetSymbolAddress((void**)&w2nh, g_w2nh); cudaGetSymbolAddress((void**)&w2nl, g_w2nl);
    cudaGetSymbolAddress((void**)&wch,  g_wch);  cudaGetSymbolAddress((void**)&wcl,  g_wcl);

    cudaFuncSetAttribute(flash_attn, cudaFuncAttributeMaxDynamicSharedMemorySize, FLASH_SMEM);
    cudaFuncSetAttribute(gemm_fh, cudaFuncAttributeMaxDynamicSharedMemorySize, GF_SMEM);

    const float scale = 1.0f / sqrtf((float)HD_);

    // 1. fused prep
    prep_all<<<(unsigned)((SW_TOTAL + 255) / 256), 256>>>(W1_self, W1_neigh, W_in,
                                                          W_out, W2_self, W2_neigh, Wc, x);
    // 2-4. CSR build
    count_deg<<<EE_ / 256, 256>>>(ei);
    scan_offsets<<<1, 1024>>>();
    csr_fill<<<EE_ / 256, 256>>>(ei);
    // 5. gather mean of x
    gather_mean_h<<<NN_, 64>>>(xh, meanh);
    // 6. SAGE1 (fp16 out)
    {
        dim3 grid(4, 32, 1);
        gemm_fh<<<grid, 512, GF_SMEM>>>(xh, meanh, KP500, w1sh, w1sl, w1nh, w1nl, KP500,
                                        b1, h1h, KP500, HH_, KP500, 1, 2, 1, 2, 0.f);
    }
    // 7. qkv projection with fused q/k/v split epilogue
    {
        dim3 grid(12, 32, 1);
        gemm_fh<<<grid, 512, GF_SMEM>>>(h1h, nullptr, KP500, winh, winl, nullptr, nullptr, KP500,
                                        b_in, nullptr, 0, 3 * HH_, KP500, 0, 3, 1, 2, scale);
    }
    // 8. flash attention (QK 2-pass)
    {
        dim3 grid(NN_ / 128, NHEAD);
        flash_attn<<<grid, 256, FLASH_SMEM>>>(qh, kh, kl, vt, attnoh);
    }
    // 9. out projection (fp16 out)
    {
        dim3 grid(4, 32, 1);
        gemm_fh<<<grid, 512, GF_SMEM>>>(attnoh, nullptr, KP500, woh, wol, nullptr, nullptr, KP500,
                                        b_out, h2h, KP500, HH_, KP500, 1, 2, 1, 2, 0.f);
    }
    // 10. gather mean of h2
    gather_mean_h<<<NN_, 64>>>(h2h, meanh);
    // 11. SAGE2 (split-K=4 atomic)
    {
        dim3 grid(1, 32, 4);
        gemm_fh<<<grid, 512, GF_SMEM>>>(h2h, meanh, KP500, w2sh, w2sl, w2nh, w2nl, KP500,
                                        nullptr, tmp2, OUT_, OUT_, KP500, 0, 1, 4, 2, 0.f);
    }
    // 12. bias+relu dual write
    bias_relu2<<<(NN_ * 128 + 255) / 256, 256>>>(tmp2, b2, out_x);
    // 13. classifier (single-pass fp16)
    {
        dim3 grid(CCP_ / 128, 32, 1);
        gemm_fh<<<grid, 512, GF_SMEM>>>(outxh, nullptr, 128, wch, wcl, nullptr, nullptr, 128,
                                        bc, out_logits, CC_, CC_, 128, 0, 0, 1, 1, 0.f);
    }
}

// round 17
// speedup vs baseline: 1.1615x; 1.0975x over previous
#include <cuda_runtime.h>
#include <cuda_fp16.h>
#include <math.h>
#include <stdint.h>

#define NN_   4096
#define EE_   131072
#define IN_   500
#define HH_   500
#define OUT_  100
#define CC_   15451
#define CCP_  15488
#define NHEAD 4
#define HD_   125
#define HDP_  128
#define KP500 512
#define NKT   (NN_ / 64)

// ---------------- scratch ----------------------------------------------------
__device__ int    g_degi[NN_];     // zero at every call entry (scan resets it)
__device__ int    g_off[NN_ + 1];
__device__ int    g_cur[NN_];
__device__ int    g_csr[EE_];
__device__ __half g_xh[NN_ * KP500];
__device__ __half g_meanh[NN_ * KP500];
__device__ __half g_h1h[NN_ * KP500];
__device__ __half g_attnoh[NN_ * KP500];   // pads stay zero forever
__device__ __half g_h2h[NN_ * KP500];
__device__ float  g_tmp2[NN_ * OUT_];
__device__ __half g_outxh[NN_ * 128];

__device__ __half g_qh[NHEAD * NN_ * HDP_];   // pads d=125..127 stay zero forever
__device__ __half g_kh[NHEAD * NN_ * HDP_];
__device__ __half g_vt[NHEAD * HDP_ * NN_];

__device__ __half g_w1sh[HH_ * KP500], g_w1sl[HH_ * KP500];
__device__ __half g_w1nh[HH_ * KP500], g_w1nl[HH_ * KP500];
__device__ __half g_winh[3 * HH_ * KP500], g_winl[3 * HH_ * KP500];
__device__ __half g_woh[HH_ * KP500], g_wol[HH_ * KP500];
__device__ __half g_w2sh[OUT_ * KP500], g_w2sl[OUT_ * KP500];
__device__ __half g_w2nh[OUT_ * KP500], g_w2nl[OUT_ * KP500];
__device__ __half g_wch[(size_t)CC_ * 128], g_wcl[(size_t)CC_ * 128];

// ---------------- helpers ----------------------------------------------------
__device__ __forceinline__ void splitf_h(float x, __half& h, __half& l) {
    h = __float2half_rn(x);
    l = __float2half_rn(x - __half2float(h));
}
__device__ __forceinline__ void split2h(float x, float y, uint32_t& hi, uint32_t& lo) {
    __half hx = __float2half_rn(x), hy = __float2half_rn(y);
    __half lx = __float2half_rn(x - __half2float(hx));
    __half ly = __float2half_rn(y - __half2float(hy));
    __half2 h2; h2.x = hx; h2.y = hy;
    __half2 l2; l2.x = lx; l2.y = ly;
    hi = *(uint32_t*)&h2;
    lo = *(uint32_t*)&l2;
}
__device__ __forceinline__ void cpasync16(void* sp, const void* gp) {
    uint32_t s = (uint32_t)__cvta_generic_to_shared(sp);
    asm volatile("cp.async.cg.shared.global [%0], [%1], 16;" :: "r"(s), "l"(gp));
}
#define CP_COMMIT() asm volatile("cp.async.commit_group;")
#define CP_WAIT(n)  asm volatile("cp.async.wait_group %0;" :: "n"(n))

#define MMA_F16(d, a, b) \
  asm volatile("mma.sync.aligned.m16n8k16.row.col.f32.f16.f16.f32 " \
   "{%0,%1,%2,%3},{%4,%5,%6,%7},{%8,%9},{%0,%1,%2,%3};" \
   : "+f"((d)[0]), "+f"((d)[1]), "+f"((d)[2]), "+f"((d)[3]) \
   : "r"((a)[0]), "r"((a)[1]), "r"((a)[2]), "r"((a)[3]), "r"((b)[0]), "r"((b)[1]))

__device__ __forceinline__ void ldmA(uint32_t* r, const __half* base, int S) {
    int l = threadIdx.x & 31;
    const __half* p = (l < 16) ? (base + l * S) : (base + (l - 16) * S + 8);
    uint32_t a = (uint32_t)__cvta_generic_to_shared(p);
    asm volatile("ldmatrix.sync.aligned.m8n8.x4.shared.b16 {%0,%1,%2,%3}, [%4];"
                 : "=r"(r[0]), "=r"(r[1]), "=r"(r[2]), "=r"(r[3]) : "r"(a));
}
__device__ __forceinline__ void ldmB(uint32_t* r, const __half* base, int S) {
    int l = threadIdx.x & 31;
    int q = l >> 3, rr = l & 7;
    const __half* p = base + (rr + ((q >> 1) << 3)) * S + ((q & 1) << 3);
    uint32_t a = (uint32_t)__cvta_generic_to_shared(p);
    asm volatile("ldmatrix.sync.aligned.m8n8.x4.shared.b16 {%0,%1,%2,%3}, [%4];"
                 : "=r"(r[0]), "=r"(r[1]), "=r"(r[2]), "=r"(r[3]) : "r"(a));
}

// ---------------- CSR --------------------------------------------------------
__global__ void count_deg(const int* __restrict__ ei) {
    int e = blockIdx.x * blockDim.x + threadIdx.x;
    if (e < EE_) atomicAdd(&g_degi[ei[EE_ + e]], 1);
}
__global__ __launch_bounds__(1024) void scan_offsets() {
    __shared__ int s[1024];
    int t = threadIdx.x;
    int base = t * 4;
    int lp[4];
    int sum = 0;
    #pragma unroll
    for (int i = 0; i < 4; i++) {
        int v = g_degi[base + i];
        g_degi[base + i] = 0;
        lp[i] = sum; sum += v;
    }
    s[t] = sum;
    __syncthreads();
    for (int off = 1; off < 1024; off <<= 1) {
        int x = (t >= off) ? s[t - off] : 0;
        __syncthreads();
        s[t] += x;
        __syncthreads();
    }
    int excl = (t > 0) ? s[t - 1] : 0;
    #pragma unroll
    for (int i = 0; i < 4; i++) {
        int o = excl + lp[i];
        g_off[base + i] = o;
        g_cur[base + i] = o;
    }
    if (t == 1023) g_off[NN_] = s[1023];
}
__global__ void csr_fill(const int* __restrict__ ei) {
    int e = blockIdx.x * blockDim.x + threadIdx.x;
    if (e >= EE_) return;
    int d = ei[EE_ + e];
    int pos = atomicAdd(&g_cur[d], 1);
    g_csr[pos] = ei[e];
}

// ---------------- fp16 gather-mean ---------------------------------------------
__global__ __launch_bounds__(64) void gather_mean_h(const __half* __restrict__ feat,
                                                    __half* __restrict__ mean) {
    int node = blockIdx.x;
    int t = threadIdx.x;
    int beg = g_off[node], end = g_off[node + 1];
    float acc[8];
    #pragma unroll
    for (int i = 0; i < 8; i++) acc[i] = 0.f;
    for (int e = beg; e < end; ++e) {
        int s0 = __ldg(&g_csr[e]);
        uint4 v = *(const uint4*)(feat + (size_t)s0 * KP500 + t * 8);
        const __half2* h2 = (const __half2*)&v;
        #pragma unroll
        for (int i = 0; i < 4; i++) {
            float2 f = __half22float2(h2[i]);
            acc[2 * i]     += f.x;
            acc[2 * i + 1] += f.y;
        }
    }
    float inv = 1.0f / fmaxf((float)(end - beg), 1.0f);
    uint4 o;
    __half2* oh = (__half2*)&o;
    #pragma unroll
    for (int i = 0; i < 4; i++)
        oh[i] = __floats2half2_rn(acc[2 * i] * inv, acc[2 * i + 1] * inv);
    *(uint4*)(mean + (size_t)node * KP500 + t * 8) = o;
}

// ---------------- fused prep -----------------------------------------------------
__device__ __forceinline__ void split_elem(const float* __restrict__ W,
                                           __half* __restrict__ hi,
                                           __half* __restrict__ lo,
                                           int Kr, int Kpad, long long local) {
    int k = (int)(local % Kpad);
    long long n = local / Kpad;
    float v = (k < Kr) ? W[n * Kr + k] : 0.f;
    splitf_h(v, hi[local], lo[local]);
}
#define SW_S0 (HH_ * KP500)
#define SW_S1 (2 * HH_ * KP500)
#define SW_S2 (SW_S1 + 3 * HH_ * KP500)
#define SW_S3 (SW_S2 + HH_ * KP500)
#define SW_S4 (SW_S3 + OUT_ * KP500)
#define SW_S5 (SW_S4 + OUT_ * KP500)
#define SW_S6 (SW_S5 + (long long)CC_ * 128)
#define SW_S7 (SW_S6 + NN_ * KP500)
#define SW_TOTAL (SW_S7 + NN_ * OUT_)

__global__ void prep_all(const float* __restrict__ W1s, const float* __restrict__ W1n,
                         const float* __restrict__ Win, const float* __restrict__ Wo,
                         const float* __restrict__ W2s, const float* __restrict__ W2n,
                         const float* __restrict__ Wc, const float* __restrict__ x) {
    long long idx = (long long)blockIdx.x * 256 + threadIdx.x;
    if (idx < SW_S0)      split_elem(W1s, g_w1sh, g_w1sl, IN_, KP500, idx);
    else if (idx < SW_S1) split_elem(W1n, g_w1nh, g_w1nl, IN_, KP500, idx - SW_S0);
    else if (idx < SW_S2) split_elem(Win, g_winh, g_winl, HH_, KP500, idx - SW_S1);
    else if (idx < SW_S3) split_elem(Wo,  g_woh,  g_wol,  HH_, KP500, idx - SW_S2);
    else if (idx < SW_S4) split_elem(W2s, g_w2sh, g_w2sl, HH_, KP500, idx - SW_S3);
    else if (idx < SW_S5) split_elem(W2n, g_w2nh, g_w2nl, HH_, KP500, idx - SW_S4);
    else if (idx < SW_S6) split_elem(Wc,  g_wch,  g_wcl,  OUT_, 128, idx - SW_S5);
    else if (idx < SW_S7) {
        long long j = idx - SW_S6;
        int col = (int)(j & (KP500 - 1));
        int n   = (int)(j >> 9);
        float v = (col < IN_) ? x[(size_t)n * IN_ + col] : 0.f;
        g_xh[j] = __float2half_rn(v);
    } else if (idx < SW_TOTAL) {
        g_tmp2[idx - SW_S7] = 0.f;
    }
}

__global__ void bias_relu2(const float* __restrict__ in, const float* __restrict__ b,
                           float* __restrict__ outf) {
    int idx = blockIdx.x * 256 + threadIdx.x;
    if (idx >= NN_ * 128) return;
    int col = idx & 127;
    int n   = idx >> 7;
    float v = 0.f;
    if (col < OUT_) {
        v = fmaxf(in[(size_t)n * OUT_ + col] + b[col], 0.f);
        outf[(size_t)n * OUT_ + col] = v;
    }
    g_outxh[idx] = __float2half_rn(v);
}

// ---------------- flash attention (QK 1-pass fp16; PV 2-pass) -------------------
#define FQS (128 * 136)
#define FKS (64 * 136)
#define FVS (128 * 72)
#define FLASH_SMEM ((FQS + 2 * FKS + 2 * FVS) * 2)

__global__ __launch_bounds__(256)
void flash_attn(const __half* __restrict__ qh,
                const __half* __restrict__ kh,
                const __half* __restrict__ vt,
                __half* __restrict__ attno) {
    extern __shared__ __half sm[];
    __half* sQh = sm;
    __half* sKb = sm + FQS;
    __half* sVb = sm + FQS + 2 * FKS;

    const int tid  = threadIdx.x;
    const int lane = tid & 31;
    const int wid  = tid >> 5;
    const int g    = lane >> 2;
    const int c    = lane & 3;
    const int bm   = blockIdx.x * 128;
    const int h    = blockIdx.y;

    const __half* qhp = qh + ((size_t)h * NN_ + bm) * HDP_;
    const __half* khp = kh + (size_t)h * NN_ * HDP_;
    const __half* vp  = vt + (size_t)h * HDP_ * NN_;

    #pragma unroll
    for (int i = 0; i < 8; i++) {
        int idx = tid + i * 256;
        int row = idx >> 4;
        int ch  = idx & 15;
        cpasync16(sQh + row * 136 + ch * 8, qhp + (size_t)row * HDP_ + ch * 8);
    }

    auto kvload = [&](int j, int buf) {
        __half* kb = sKb + buf * FKS;
        __half* vb = sVb + buf * FVS;
        const int key0 = j * 64;
        #pragma unroll
        for (int i = 0; i < 4; i++) {
            int idx = tid + i * 256;
            int row = idx >> 4;
            int ch  = idx & 15;
            cpasync16(kb + row * 136 + ch * 8,
                      khp + (size_t)(key0 + row) * HDP_ + ch * 8);
        }
        #pragma unroll
        for (int i = 0; i < 4; i++) {
            int idx = tid + i * 256;
            int row = idx >> 3;
            int ch  = idx & 7;
            cpasync16(vb + row * 72 + ch * 8,
                      vp + (size_t)row * NN_ + key0 + ch * 8);
        }
    };

    kvload(0, 0);
    CP_COMMIT();

    float m0 = -1e30f, m1 = -1e30f, l0 = 0.f, l1 = 0.f;
    float acco[16][4];
    #pragma unroll
    for (int i = 0; i < 16; i++)
        #pragma unroll
        for (int q = 0; q < 4; q++) acco[i][q] = 0.f;

    const int arow = wid * 16 + g;

    for (int j = 0; j < NKT; ++j) {
        if (j + 1 < NKT) {
            kvload(j + 1, (j + 1) & 1);
            CP_COMMIT();
            CP_WAIT(1);
        } else {
            CP_WAIT(0);
        }
        __syncthreads();

        const __half* kbh = sKb + (j & 1) * FKS;
        const __half* vb  = sVb + (j & 1) * FVS;

        float accs[8][4];
        #pragma unroll
        for (int i = 0; i < 8; i++)
            #pragma unroll
            for (int q = 0; q < 4; q++) accs[i][q] = 0.f;

        // ---- S = Q @ K^T (1-pass fp16) ----
        #pragma unroll
        for (int ks = 0; ks < 8; ++ks) {
            uint32_t ahh[4];
            ldmA(ahh, sQh + (wid * 16) * 136 + ks * 16, 136);
            #pragma unroll
            for (int ntp = 0; ntp < 4; ++ntp) {
                uint32_t bh4[4];
                ldmB(bh4, kbh + (ntp * 16) * 136 + ks * 16, 136);
                #pragma unroll
                for (int half = 0; half < 2; ++half) {
                    uint32_t bh[2] = {bh4[half * 2], bh4[half * 2 + 1]};
                    MMA_F16(accs[ntp * 2 + half], ahh, bh);
                }
            }
        }

        float t0 = -1e30f, t1 = -1e30f;
        #pragma unroll
        for (int nt = 0; nt < 8; ++nt) {
            t0 = fmaxf(t0, fmaxf(accs[nt][0], accs[nt][1]));
            t1 = fmaxf(t1, fmaxf(accs[nt][2], accs[nt][3]));
        }
        t0 = fmaxf(t0, __shfl_xor_sync(0xffffffffu, t0, 1));
        t0 = fmaxf(t0, __shfl_xor_sync(0xffffffffu, t0, 2));
        t1 = fmaxf(t1, __shfl_xor_sync(0xffffffffu, t1, 1));
        t1 = fmaxf(t1, __shfl_xor_sync(0xffffffffu, t1, 2));
        float nm0 = fmaxf(m0, t0), nm1 = fmaxf(m1, t1);
        float sc0 = __expf(m0 - nm0), sc1 = __expf(m1 - nm1);

        uint32_t ph[4][4], pl[4][4];
        float ps0 = 0.f, ps1 = 0.f;
        #pragma unroll
        for (int kk = 0; kk < 4; ++kk) {
            float p00 = __expf(accs[2 * kk][0] - nm0);
            float p01 = __expf(accs[2 * kk][1] - nm0);
            float p02 = __expf(accs[2 * kk][2] - nm1);
            float p03 = __expf(accs[2 * kk][3] - nm1);
            float p10 = __expf(accs[2 * kk + 1][0] - nm0);
            float p11 = __expf(accs[2 * kk + 1][1] - nm0);
            float p12 = __expf(accs[2 * kk + 1][2] - nm1);
            float p13 = __expf(accs[2 * kk + 1][3] - nm1);
            ps0 += p00 + p01 + p10 + p11;
            ps1 += p02 + p03 + p12 + p13;
            split2h(p00, p01, ph[kk][0], pl[kk][0]);
            split2h(p02, p03, ph[kk][1], pl[kk][1]);
            split2h(p10, p11, ph[kk][2], pl[kk][2]);
            split2h(p12, p13, ph[kk][3], pl[kk][3]);
        }
        ps0 += __shfl_xor_sync(0xffffffffu, ps0, 1);
        ps0 += __shfl_xor_sync(0xffffffffu, ps0, 2);
        ps1 += __shfl_xor_sync(0xffffffffu, ps1, 1);
        ps1 += __shfl_xor_sync(0xffffffffu, ps1, 2);
        l0 = l0 * sc0 + ps0;
        l1 = l1 * sc1 + ps1;
        m0 = nm0;
        m1 = nm1;

        #pragma unroll
        for (int nt = 0; nt < 16; ++nt) {
            acco[nt][0] *= sc0; acco[nt][1] *= sc0;
            acco[nt][2] *= sc1; acco[nt][3] *= sc1;
        }

        #pragma unroll
        for (int ntp = 0; ntp < 8; ++ntp) {
            #pragma unroll
            for (int kk = 0; kk < 4; ++kk) {
                uint32_t v4[4];
                ldmB(v4, vb + (ntp * 16) * 72 + kk * 16, 72);
                #pragma unroll
                for (int half = 0; half < 2; ++half) {
                    uint32_t bv[2] = {v4[half * 2], v4[half * 2 + 1]};
                    int nt = ntp * 2 + half;
                    MMA_F16(acco[nt], ph[kk], bv);
                    MMA_F16(acco[nt], pl[kk], bv);
                }
            }
        }
        __syncthreads();
    }

    float i0 = 1.0f / l0, i1 = 1.0f / l1;
    int r0 = bm + arow;
    #pragma unroll
    for (int nt = 0; nt < 16; ++nt) {
        int col = nt * 8 + c * 2;
        if (col < HD_) {
            attno[(size_t)r0 * KP500 + h * HD_ + col]       = __float2half_rn(acco[nt][0] * i0);
            attno[(size_t)(r0 + 8) * KP500 + h * HD_ + col] = __float2half_rn(acco[nt][2] * i1);
        }
        if (col + 1 < HD_) {
            attno[(size_t)r0 * KP500 + h * HD_ + col + 1]       = __float2half_rn(acco[nt][1] * i0);
            attno[(size_t)(r0 + 8) * KP500 + h * HD_ + col + 1] = __float2half_rn(acco[nt][3] * i1);
        }
    }
}

// ---------------- fp16 GEMM with 3-stage cp.async pipeline -----------------------
#define GF_CH 5120
#define GF_SMEM (9 * GF_CH * 2)

__global__ __launch_bounds__(512, 1)
void gemm_fh(const __half* __restrict__ A1, const __half* __restrict__ A2, int lda,
             const __half* __restrict__ B1h, const __half* __restrict__ B1l,
             const __half* __restrict__ B2h, const __half* __restrict__ B2l,
             int ldb,
             const float* __restrict__ bias,
             void* __restrict__ C_, int ldc,
             int Nfull, int Kpad, int relu, int mode, int ksplit,
             int npassB, float qscale) {
    extern __shared__ __half gsm[];
    __half* sA  = gsm;
    __half* sBh = gsm + 3 * GF_CH;
    __half* sBl = gsm + 6 * GF_CH;

    const int tid  = threadIdx.x;
    const int lane = tid & 31;
    const int wid  = tid >> 5;
    const int wm   = wid & 3;
    const int wn   = wid >> 2;
    const int bm   = blockIdx.y * 128;
    const int bn   = blockIdx.x * 128;
    const int ks   = blockIdx.z % ksplit;
    const int klen = Kpad / ksplit;
    const int kb   = ks * klen;
    const int nchunk = klen / 32;
    const int npairs = (A2 != nullptr) ? 2 : 1;
    const int total  = npairs * nchunk;

    const int r  = tid >> 2;
    const int gq = tid & 3;
    const bool bok = (bn + r) < Nfull;

    if (!bok) {
        #pragma unroll
        for (int s = 0; s < 3; ++s) {
            *(uint4*)(sBh + s * GF_CH + r * 40 + gq * 8) = make_uint4(0, 0, 0, 0);
            *(uint4*)(sBl + s * GF_CH + r * 40 + gq * 8) = make_uint4(0, 0, 0, 0);
        }
    }

    float acc[2][4][4];
    #pragma unroll
    for (int i = 0; i < 2; i++)
        #pragma unroll
        for (int j = 0; j < 4; j++)
            #pragma unroll
            for (int q = 0; q < 4; q++) acc[i][j][q] = 0.f;

    auto issue = [&](int ci, int st) {
        int pr = ci / nchunk;
        int k0 = kb + (ci - pr * nchunk) * 32;
        const __half* A  = pr ? A2 : A1;
        cpasync16(sA + st * GF_CH + r * 40 + gq * 8,
                  A + (size_t)(bm + r) * lda + k0 + gq * 8);
        if (bok) {
            const __half* Bh = pr ? B2h : B1h;
            cpasync16(sBh + st * GF_CH + r * 40 + gq * 8,
                      Bh + (size_t)(bn + r) * ldb + k0 + gq * 8);
            if (npassB > 1) {
                const __half* Bl = pr ? B2l : B1l;
                cpasync16(sBl + st * GF_CH + r * 40 + gq * 8,
                          Bl + (size_t)(bn + r) * ldb + k0 + gq * 8);
            }
        }
        CP_COMMIT();
    };

    issue(0, 0);
    issue(1, 1);

    for (int ci = 0; ci < total; ++ci) {
        if (ci + 1 < total) { CP_WAIT(1); } else { CP_WAIT(0); }
        __syncthreads();
        if (ci + 2 < total) issue(ci + 2, (ci + 2) % 3);

        const int st = ci % 3;
        const __half* cA  = sA  + st * GF_CH;
        const __half* cBh = sBh + st * GF_CH;
        const __half* cBl = sBl + st * GF_CH;

        #pragma unroll
        for (int ksf = 0; ksf < 2; ++ksf) {
            uint32_t a[2][4];
            #pragma unroll
            for (int mt = 0; mt < 2; ++mt)
                ldmA(a[mt], cA + (wm * 32 + mt * 16) * 40 + ksf * 16, 40);
            #pragma unroll
            for (int ntp = 0; ntp < 2; ++ntp) {
                uint32_t bh4[4], bl4[4];
                ldmB(bh4, cBh + (wn * 32 + ntp * 16) * 40 + ksf * 16, 40);
                if (npassB > 1)
                    ldmB(bl4, cBl + (wn * 32 + ntp * 16) * 40 + ksf * 16, 40);
                #pragma unroll
                for (int half = 0; half < 2; ++half) {
                    uint32_t bh[2] = {bh4[half * 2], bh4[half * 2 + 1]};
                    int nt = ntp * 2 + half;
                    #pragma unroll
                    for (int mt = 0; mt < 2; ++mt)
                        MMA_F16(acc[mt][nt], a[mt], bh);
                    if (npassB > 1) {
                        uint32_t bl[2] = {bl4[half * 2], bl4[half * 2 + 1]};
                        #pragma unroll
                        for (int mt = 0; mt < 2; ++mt)
                            MMA_F16(acc[mt][nt], a[mt], bl);
                    }
                }
            }
        }
    }

    if (mode == 0) {
        float* C = (float*)C_;
        #pragma unroll
        for (int mt = 0; mt < 2; ++mt) {
            int row = bm + wm * 32 + mt * 16 + (lane >> 2);
            #pragma unroll
            for (int nt = 0; nt < 4; ++nt) {
                int gc = bn + wn * 32 + nt * 8 + ((lane & 3) << 1);
                #pragma unroll
                for (int j = 0; j < 2; ++j) {
                    if (gc + j < Nfull) {
                        float bsv = bias ? bias[gc + j] : 0.f;
                        float v0 = acc[mt][nt][j] + bsv;
                        float v1 = acc[mt][nt][j + 2] + bsv;
                        if (relu) { v0 = fmaxf(v0, 0.f); v1 = fmaxf(v1, 0.f); }
                        C[(size_t)row * ldc + gc + j] = v0;
                        C[(size_t)(row + 8) * ldc + gc + j] = v1;
                    }
                }
            }
        }
    } else if (mode == 1) {
        float* C = (float*)C_;
        #pragma unroll
        for (int mt = 0; mt < 2; ++mt) {
            int row = bm + wm * 32 + mt * 16 + (lane >> 2);
            #pragma unroll
            for (int nt = 0; nt < 4; ++nt) {
                int gc = bn + wn * 32 + nt * 8 + ((lane & 3) << 1);
                #pragma unroll
                for (int j = 0; j < 2; ++j) {
                    if (gc + j < Nfull) {
                        atomicAdd(&C[(size_t)row * ldc + gc + j], acc[mt][nt][j]);
                        atomicAdd(&C[(size_t)(row + 8) * ldc + gc + j], acc[mt][nt][j + 2]);
                    }
                }
            }
        }
    } else if (mode == 2) {
        __half* C = (__half*)C_;
        #pragma unroll
        for (int mt = 0; mt < 2; ++mt) {
            int row = bm + wm * 32 + mt * 16 + (lane >> 2);
            #pragma unroll
            for (int nt = 0; nt < 4; ++nt) {
                int gc = bn + wn * 32 + nt * 8 + ((lane & 3) << 1);
                #pragma unroll
                for (int j = 0; j < 2; ++j) {
                    float v0 = 0.f, v1 = 0.f;
                    if (gc + j < Nfull) {
                        float bsv = bias ? bias[gc + j] : 0.f;
                        v0 = acc[mt][nt][j] + bsv;
                        v1 = acc[mt][nt][j + 2] + bsv;
                        if (relu) { v0 = fmaxf(v0, 0.f); v1 = fmaxf(v1, 0.f); }
                    }
                    C[(size_t)row * ldc + gc + j] = __float2half_rn(v0);
                    C[(size_t)(row + 8) * ldc + gc + j] = __float2half_rn(v1);
                }
            }
        }
    } else {
        // mode 3: qkv split epilogue (q: hi, scaled; k: hi; v: transposed)
        #pragma unroll
        for (int mt = 0; mt < 2; ++mt) {
            int n0 = bm + wm * 32 + mt * 16 + (lane >> 2);
            int n1 = n0 + 8;
            #pragma unroll
            for (int nt = 0; nt < 4; ++nt) {
                int gc = bn + wn * 32 + nt * 8 + ((lane & 3) << 1);
                #pragma unroll
                for (int j = 0; j < 2; ++j) {
                    int cc = gc + j;
                    if (cc >= 3 * HH_) continue;
                    float v0 = acc[mt][nt][j]     + bias[cc];
                    float v1 = acc[mt][nt][j + 2] + bias[cc];
                    if (cc < HH_) {
                        int h = cc / HD_;
                        int d = cc - h * HD_;
                        size_t b0 = ((size_t)h * NN_ + n0) * HDP_ + d;
                        size_t b1 = ((size_t)h * NN_ + n1) * HDP_ + d;
                        g_qh[b0] = __float2half_rn(v0 * qscale);
                        g_qh[b1] = __float2half_rn(v1 * qscale);
                    } else if (cc < 2 * HH_) {
                        int c2 = cc - HH_;
                        int h = c2 / HD_;
                        int d = c2 - h * HD_;
                        size_t b0 = ((size_t)h * NN_ + n0) * HDP_ + d;
                        size_t b1 = ((size_t)h * NN_ + n1) * HDP_ + d;
                        g_kh[b0] = __float2half_rn(v0);
                        g_kh[b1] = __float2half_rn(v1);
                    } else {
                        int c2 = cc - 2 * HH_;
                        int h = c2 / HD_;
                        int d = c2 - h * HD_;
                        size_t base = ((size_t)h * HDP_ + d) * NN_;
                        g_vt[base + n0] = __float2half_rn(v0);
                        g_vt[base + n1] = __float2half_rn(v1);
                    }
                }
            }
        }
    }
}

// ---------------- launch -----------------------------------------------------
extern "C" void kernel_launch(void* const* d_in, const int* in_sizes, int n_in,
                              void* d_out, int out_size) {
    const float* x        = (const float*)d_in[0];
    const int*   ei       = (const int*)d_in[1];
    const float* W1_self  = (const float*)d_in[2];
    const float* W1_neigh = (const float*)d_in[3];
    const float* b1       = (const float*)d_in[4];
    const float* W_in     = (const float*)d_in[5];
    const float* b_in     = (const float*)d_in[6];
    const float* W_out    = (const float*)d_in[7];
    const float* b_out    = (const float*)d_in[8];
    const float* W2_self  = (const float*)d_in[9];
    const float* W2_neigh = (const float*)d_in[10];
    const float* b2       = (const float*)d_in[11];
    const float* Wc       = (const float*)d_in[12];
    const float* bc       = (const float*)d_in[13];

    float* out_x      = (float*)d_out;
    float* out_logits = (float*)d_out + (size_t)NN_ * OUT_;

    float* tmp2;
    __half *xh, *meanh, *h1h, *attnoh, *h2h, *outxh;
    cudaGetSymbolAddress((void**)&xh,     g_xh);
    cudaGetSymbolAddress((void**)&meanh,  g_meanh);
    cudaGetSymbolAddress((void**)&h1h,    g_h1h);
    cudaGetSymbolAddress((void**)&attnoh, g_attnoh);
    cudaGetSymbolAddress((void**)&h2h,    g_h2h);
    cudaGetSymbolAddress((void**)&tmp2,   g_tmp2);
    cudaGetSymbolAddress((void**)&outxh,  g_outxh);

    __half *qh, *kh, *vt;
    __half *w1sh, *w1sl, *w1nh, *w1nl, *winh, *winl, *woh, *wol;
    __half *w2sh, *w2sl, *w2nh, *w2nl, *wch, *wcl;
    cudaGetSymbolAddress((void**)&qh,   g_qh);
    cudaGetSymbolAddress((void**)&kh,   g_kh);
    cudaGetSymbolAddress((void**)&vt,   g_vt);
    cudaGetSymbolAddress((void**)&w1sh, g_w1sh); cudaGetSymbolAddress((void**)&w1sl, g_w1sl);
    cudaGetSymbolAddress((void**)&w1nh, g_w1nh); cudaGetSymbolAddress((void**)&w1nl, g_w1nl);
    cudaGetSymbolAddress((void**)&winh, g_winh); cudaGetSymbolAddress((void**)&winl, g_winl);
    cudaGetSymbolAddress((void**)&woh,  g_woh);  cudaGetSymbolAddress((void**)&wol,  g_wol);
    cudaGetSymbolAddress((void**)&w2sh, g_w2sh); cudaGetSymbolAddress((void**)&w2sl, g_w2sl);
    cudaGetSymbolAddress((void**)&w2nh, g_w2nh); cudaGetSymbolAddress((void**)&w2nl, g_w2nl);
    cudaGetSymbolAddress((void**)&wch,  g_wch);  cudaGetSymbolAddress((void**)&wcl,  g_wcl);

    cudaFuncSetAttribute(flash_attn, cudaFuncAttributeMaxDynamicSharedMemorySize, FLASH_SMEM);
    cudaFuncSetAttribute(gemm_fh, cudaFuncAttributeMaxDynamicSharedMemorySize, GF_SMEM);

    const float scale = 1.0f / sqrtf((float)HD_);

    // 1. fused prep
    prep_all<<<(unsigned)((SW_TOTAL + 255) / 256), 256>>>(W1_self, W1_neigh, W_in,
                                                          W_out, W2_self, W2_neigh, Wc, x);
    // 2-4. CSR build
    count_deg<<<EE_ / 256, 256>>>(ei);
    scan_offsets<<<1, 1024>>>();
    csr_fill<<<EE_ / 256, 256>>>(ei);
    // 5. gather mean of x
    gather_mean_h<<<NN_, 64>>>(xh, meanh);
    // 6. SAGE1 (fp16 out)
    {
        dim3 grid(4, 32, 1);
        gemm_fh<<<grid, 512, GF_SMEM>>>(xh, meanh, KP500, w1sh, w1sl, w1nh, w1nl, KP500,
                                        b1, h1h, KP500, HH_, KP500, 1, 2, 1, 2, 0.f);
    }
    // 7. qkv projection with fused q/k/v split epilogue
    {
        dim3 grid(12, 32, 1);
        gemm_fh<<<grid, 512, GF_SMEM>>>(h1h, nullptr, KP500, winh, winl, nullptr, nullptr, KP500,
                                        b_in, nullptr, 0, 3 * HH_, KP500, 0, 3, 1, 2, scale);
    }
    // 8. flash attention (QK 1-pass)
    {
        dim3 grid(NN_ / 128, NHEAD);
        flash_attn<<<grid, 256, FLASH_SMEM>>>(qh, kh, vt, attnoh);
    }
    // 9. out projection (fp16 out)
    {
        dim3 grid(4, 32, 1);
        gemm_fh<<<grid, 512, GF_SMEM>>>(attnoh, nullptr, KP500, woh, wol, nullptr, nullptr, KP500,
                                        b_out, h2h, KP500, HH_, KP500, 1, 2, 1, 2, 0.f);
    }
    // 10. gather mean of h2
    gather_mean_h<<<NN_, 64>>>(h2h, meanh);
    // 11. SAGE2 (split-K=4 atomic)
    {
        dim3 grid(1, 32, 4);
        gemm_fh<<<grid, 512, GF_SMEM>>>(h2h, meanh, KP500, w2sh, w2sl, w2nh, w2nl, KP500,
                                        nullptr, tmp2, OUT_, OUT_, KP500, 0, 1, 4, 2, 0.f);
    }
    // 12. bias+relu dual write
    bias_relu2<<<(NN_ * 128 + 255) / 256, 256>>>(tmp2, b2, out_x);
    // 13. classifier (single-pass fp16)
    {
        dim3 grid(CCP_ / 128, 32, 1);
        gemm_fh<<<grid, 512, GF_SMEM>>>(outxh, nullptr, 128, wch, wcl, nullptr, nullptr, 128,
                                        bc, out_logits, CC_, CC_, 128, 0, 0, 1, 1, 0.f);
    }
}